// round 1
// baseline (speedup 1.0000x reference)
#include <cuda_runtime.h>
#include <math.h>

#define Bb 8
#define Tt 64
#define Nn 128
#define Dd 512
#define KHh 8
#define DHh 64
#define KSz 3
#define EPSv 1e-5f

#define NELEM (Bb*Tt*Nn*Dd)   // 16,777,216

// ---- device scratch (allocation-free per harness rules) ----
static __device__ float g_Q[NELEM];
static __device__ float g_K[NELEM];
static __device__ float g_V[NELEM];
static __device__ float g_AO[NELEM];
static __device__ float g_wq[KSz*Dd*Dd];
static __device__ float g_wk[KSz*Dd*Dd];
static __device__ float g_wv[Dd*Dd];
static __device__ float g_wo[Dd*Dd];
static __device__ float g_qsc[Dd], g_qsh[Dd];
static __device__ float g_ksc[Dd], g_ksh[Dd];

// ---------------- prep kernels ----------------
// conv weight: src [e, d, 1, s] -> dst [s][d][e]
__global__ void repack_conv(const float* __restrict__ W, float* __restrict__ out) {
    int idx = blockIdx.x * blockDim.x + threadIdx.x;
    if (idx >= KSz * Dd * Dd) return;
    int s = idx / (Dd * Dd);
    int r = idx - s * Dd * Dd;
    int d = r / Dd;
    int e = r - d * Dd;
    out[idx] = W[(e * Dd + d) * KSz + s];
}

// fc weight: src [e, d] -> dst [d][e]
__global__ void repack_fc(const float* __restrict__ W, float* __restrict__ out) {
    int idx = blockIdx.x * blockDim.x + threadIdx.x;
    if (idx >= Dd * Dd) return;
    int d = idx / Dd;
    int e = idx - d * Dd;
    out[idx] = W[e * Dd + d];
}

// fold conv bias + eval-mode BN into per-channel scale/shift:
// y = (conv + b - m) * g*rsqrt(v+eps) + beta = conv*sc + (beta + (b-m)*sc)
__global__ void affine_k(const float* __restrict__ bc, const float* __restrict__ g,
                         const float* __restrict__ beta, const float* __restrict__ m,
                         const float* __restrict__ v, float* __restrict__ scale,
                         float* __restrict__ shift) {
    int e = blockIdx.x * blockDim.x + threadIdx.x;
    if (e >= Dd) return;
    float sc = g[e] * rsqrtf(v[e] + EPSv);
    scale[e] = sc;
    shift[e] = beta[e] + (bc[e] - m[e]) * sc;
}

// ---------------- conv-GEMM ----------------
// Computes Out[(bt, n), e] = sum_s sum_d A[(b, t-(ntaps-1)+s, n), d] * Wr[s][d][e]
// then per-channel affine (scale may be null => 1, shift may be null => 0).
// Grid: (Dd/64, Nn/64, Bb*Tt), 256 threads, 64x64 tile, BK=16, 4x4 per thread.
__global__ void __launch_bounds__(256) gemm_conv(
    const float* __restrict__ A, const float* __restrict__ Wr, int ntaps,
    const float* __restrict__ scale, const float* __restrict__ shift,
    float* __restrict__ Out)
{
    __shared__ float As[16][68];   // [k][m], padded for bank/alignment
    __shared__ float Bs[16][64];   // [k][e]

    const int bt = blockIdx.z;
    const int t  = bt % Tt;
    const int n0 = blockIdx.y * 64;
    const int e0 = blockIdx.x * 64;
    const int tid = threadIdx.x;

    // A-load mapping: each thread loads one float4 (row lm, cols lk4..lk4+3)
    const int lm  = tid >> 2;
    const int lk4 = (tid & 3) * 4;
    // B-load mapping
    const int bk  = tid >> 4;
    const int be4 = (tid & 15) * 4;
    // compute mapping: 16x16 thread grid, 4x4 micro-tile
    const int tm = (tid >> 4) * 4;
    const int te = (tid & 15) * 4;

    float acc[4][4];
#pragma unroll
    for (int i = 0; i < 4; ++i)
#pragma unroll
        for (int j = 0; j < 4; ++j) acc[i][j] = 0.0f;

    const size_t slab = (size_t)Nn * Dd;

    for (int s = 0; s < ntaps; ++s) {
        const int t_in = t - (ntaps - 1) + s;
        if (t_in < 0) continue;   // zero padding of causal conv
        const float* Ab = A + (size_t)(bt - t + t_in) * slab + (size_t)n0 * Dd;
        const float* Wb = Wr + (size_t)s * Dd * Dd + e0;

        for (int kk = 0; kk < Dd; kk += 16) {
            float4 av = *(const float4*)(Ab + (size_t)lm * Dd + kk + lk4);
            As[lk4 + 0][lm] = av.x;
            As[lk4 + 1][lm] = av.y;
            As[lk4 + 2][lm] = av.z;
            As[lk4 + 3][lm] = av.w;
            *(float4*)&Bs[bk][be4] = *(const float4*)(Wb + (size_t)(kk + bk) * Dd + be4);
            __syncthreads();
#pragma unroll
            for (int k = 0; k < 16; ++k) {
                float4 a = *(const float4*)&As[k][tm];
                float4 b = *(const float4*)&Bs[k][te];
                acc[0][0] += a.x * b.x; acc[0][1] += a.x * b.y; acc[0][2] += a.x * b.z; acc[0][3] += a.x * b.w;
                acc[1][0] += a.y * b.x; acc[1][1] += a.y * b.y; acc[1][2] += a.y * b.z; acc[1][3] += a.y * b.w;
                acc[2][0] += a.z * b.x; acc[2][1] += a.z * b.y; acc[2][2] += a.z * b.z; acc[2][3] += a.z * b.w;
                acc[3][0] += a.w * b.x; acc[3][1] += a.w * b.y; acc[3][2] += a.w * b.z; acc[3][3] += a.w * b.w;
            }
            __syncthreads();
        }
    }

    // epilogue: per-channel affine, vectorized store
    float s0 = 1.f, s1 = 1.f, s2 = 1.f, s3 = 1.f;
    float h0 = 0.f, h1 = 0.f, h2 = 0.f, h3 = 0.f;
    const int e = e0 + te;
    if (scale) { s0 = scale[e]; s1 = scale[e+1]; s2 = scale[e+2]; s3 = scale[e+3]; }
    if (shift) { h0 = shift[e]; h1 = shift[e+1]; h2 = shift[e+2]; h3 = shift[e+3]; }
#pragma unroll
    for (int i = 0; i < 4; ++i) {
        const int m = tm + i;
        float4 o;
        o.x = acc[i][0] * s0 + h0;
        o.y = acc[i][1] * s1 + h1;
        o.z = acc[i][2] * s2 + h2;
        o.w = acc[i][3] * s3 + h3;
        *(float4*)(Out + ((size_t)bt * Nn + (n0 + m)) * Dd + e) = o;
    }
}

// ---------------- attention ----------------
// One block per (b, n, h): Q/K/V tiles 64x64 in smem, full (non-causal) softmax.
#define SMEM_ATTN ((64*68 + 64*68 + 64*64 + 64*65) * 4)

__global__ void __launch_bounds__(256) attn_kernel(
    const float* __restrict__ Q, const float* __restrict__ K,
    const float* __restrict__ V, float* __restrict__ O)
{
    extern __shared__ float sm[];
    float* Qs = sm;               // [64][68]
    float* Ks = Qs + 64 * 68;     // [64][68]
    float* Vs = Ks + 64 * 68;     // [64][64]
    float* At = Vs + 64 * 64;     // [64][65]

    const int blk = blockIdx.x;
    const int h = blk & (KHh - 1);
    const int n = (blk >> 3) & (Nn - 1);
    const int b = blk >> 10;

    const int tid = threadIdx.x;
    const int r  = tid >> 2;          // row (t) this thread owns
    const int c0 = (tid & 3) * 16;    // 16-wide column slice

    const size_t tstride = (size_t)Nn * Dd;
    const size_t base = ((size_t)b * Tt * Nn + n) * Dd + h * DHh;

    // cooperative load of Q, K, V tiles
#pragma unroll
    for (int j = 0; j < 16; j += 4) {
        const size_t g = base + (size_t)r * tstride + c0 + j;
        *(float4*)&Qs[r * 68 + c0 + j] = *(const float4*)(Q + g);
        *(float4*)&Ks[r * 68 + c0 + j] = *(const float4*)(K + g);
        *(float4*)&Vs[r * 64 + c0 + j] = *(const float4*)(V + g);
    }
    __syncthreads();

    // scores: thread (q=r, p in [c0, c0+16))
    float acc[16];
#pragma unroll
    for (int p = 0; p < 16; ++p) acc[p] = 0.0f;
    for (int d = 0; d < 64; d += 4) {
        float4 qv = *(const float4*)&Qs[r * 68 + d];
#pragma unroll
        for (int pp = 0; pp < 16; ++pp) {
            float4 kv = *(const float4*)&Ks[(c0 + pp) * 68 + d];
            acc[pp] += qv.x * kv.x + qv.y * kv.y + qv.z * kv.z + qv.w * kv.w;
        }
    }

    // softmax across the 4 lanes sharing row r (lane groups of 4, xor 1/2 stays in-group)
    float mx = -1e30f;
#pragma unroll
    for (int pp = 0; pp < 16; ++pp) { acc[pp] *= 0.125f; mx = fmaxf(mx, acc[pp]); }
    mx = fmaxf(mx, __shfl_xor_sync(0xffffffffu, mx, 1));
    mx = fmaxf(mx, __shfl_xor_sync(0xffffffffu, mx, 2));
    float sum = 0.0f;
#pragma unroll
    for (int pp = 0; pp < 16; ++pp) { acc[pp] = __expf(acc[pp] - mx); sum += acc[pp]; }
    sum += __shfl_xor_sync(0xffffffffu, sum, 1);
    sum += __shfl_xor_sync(0xffffffffu, sum, 2);
    const float inv = 1.0f / sum;
#pragma unroll
    for (int pp = 0; pp < 16; ++pp) At[r * 65 + c0 + pp] = acc[pp] * inv;
    __syncthreads();

    // out[q, d0..d0+16) = sum_p attn[q][p] * V[p][d]
    float o[16];
#pragma unroll
    for (int j = 0; j < 16; ++j) o[j] = 0.0f;
    for (int p = 0; p < 64; ++p) {
        const float av = At[r * 65 + p];
#pragma unroll
        for (int j4 = 0; j4 < 16; j4 += 4) {
            float4 vv = *(const float4*)&Vs[p * 64 + c0 + j4];
            o[j4 + 0] += av * vv.x;
            o[j4 + 1] += av * vv.y;
            o[j4 + 2] += av * vv.z;
            o[j4 + 3] += av * vv.w;
        }
    }
#pragma unroll
    for (int j4 = 0; j4 < 16; j4 += 4) {
        *(float4*)(O + base + (size_t)r * tstride + c0 + j4) =
            make_float4(o[j4], o[j4 + 1], o[j4 + 2], o[j4 + 3]);
    }
}

// ---------------- launch ----------------
extern "C" void kernel_launch(void* const* d_in, const int* in_sizes, int n_in,
                              void* d_out, int out_size)
{
    const float* X     = (const float*)d_in[0];
    const float* Wq    = (const float*)d_in[1];
    const float* bq    = (const float*)d_in[2];
    const float* gq    = (const float*)d_in[3];
    const float* betaq = (const float*)d_in[4];
    const float* mq    = (const float*)d_in[5];
    const float* vq    = (const float*)d_in[6];
    const float* Wk    = (const float*)d_in[7];
    const float* bk    = (const float*)d_in[8];
    const float* gk    = (const float*)d_in[9];
    const float* betak = (const float*)d_in[10];
    const float* mk    = (const float*)d_in[11];
    const float* vk    = (const float*)d_in[12];
    const float* Wv    = (const float*)d_in[13];
    const float* bv    = (const float*)d_in[14];
    const float* Wo    = (const float*)d_in[15];
    const float* bo    = (const float*)d_in[16];
    float* out = (float*)d_out;

    float *pQ, *pK, *pV, *pAO, *pwq, *pwk, *pwv, *pwo;
    float *pqsc, *pqsh, *pksc, *pksh;
    cudaGetSymbolAddress((void**)&pQ,  g_Q);
    cudaGetSymbolAddress((void**)&pK,  g_K);
    cudaGetSymbolAddress((void**)&pV,  g_V);
    cudaGetSymbolAddress((void**)&pAO, g_AO);
    cudaGetSymbolAddress((void**)&pwq, g_wq);
    cudaGetSymbolAddress((void**)&pwk, g_wk);
    cudaGetSymbolAddress((void**)&pwv, g_wv);
    cudaGetSymbolAddress((void**)&pwo, g_wo);
    cudaGetSymbolAddress((void**)&pqsc, g_qsc);
    cudaGetSymbolAddress((void**)&pqsh, g_qsh);
    cudaGetSymbolAddress((void**)&pksc, g_ksc);
    cudaGetSymbolAddress((void**)&pksh, g_ksh);

    repack_conv<<<(KSz*Dd*Dd + 255)/256, 256>>>(Wq, pwq);
    repack_conv<<<(KSz*Dd*Dd + 255)/256, 256>>>(Wk, pwk);
    repack_fc<<<(Dd*Dd + 255)/256, 256>>>(Wv, pwv);
    repack_fc<<<(Dd*Dd + 255)/256, 256>>>(Wo, pwo);
    affine_k<<<2, 256>>>(bq, gq, betaq, mq, vq, pqsc, pqsh);
    affine_k<<<2, 256>>>(bk, gk, betak, mk, vk, pksc, pksh);

    dim3 grid(Dd/64, Nn/64, Bb*Tt);
    gemm_conv<<<grid, 256>>>(X, pwq, KSz, pqsc, pqsh, pQ);
    gemm_conv<<<grid, 256>>>(X, pwk, KSz, pksc, pksh, pK);
    gemm_conv<<<grid, 256>>>(X, pwv, 1, nullptr, bv, pV);

    cudaFuncSetAttribute(attn_kernel, cudaFuncAttributeMaxDynamicSharedMemorySize, SMEM_ATTN);
    attn_kernel<<<Bb*Nn*KHh, 256, SMEM_ATTN>>>(pQ, pK, pV, pAO);

    gemm_conv<<<grid, 256>>>(pAO, pwo, 1, nullptr, bo, out);
}

// round 3
// speedup vs baseline: 2.2524x; 2.2524x over previous
#include <cuda_runtime.h>
#include <cuda_bf16.h>
#include <cstdint>
#include <math.h>

#define Bb 8
#define Tt 64
#define Nn 128
#define Dd 512
#define KHh 8
#define DHh 64
#define KSz 3
#define EPSv 1e-5f

#define NELEM (Bb*Tt*Nn*Dd)   // 16,777,216

// ======================= device scratch =======================
static __device__ float g_Q[NELEM];
static __device__ float g_K[NELEM];
static __device__ float g_V[NELEM];
static __device__ float g_AO[NELEM];
static __device__ __nv_bfloat16 g_Xhi[NELEM];
static __device__ __nv_bfloat16 g_Xlo[NELEM];
static __device__ __nv_bfloat16 g_AOhi[NELEM];
static __device__ __nv_bfloat16 g_AOlo[NELEM];
static __device__ __nv_bfloat16 g_wqhi[KSz*Dd*Dd], g_wqlo[KSz*Dd*Dd];
static __device__ __nv_bfloat16 g_wkhi[KSz*Dd*Dd], g_wklo[KSz*Dd*Dd];
static __device__ __nv_bfloat16 g_wvhi[Dd*Dd], g_wvlo[Dd*Dd];
static __device__ __nv_bfloat16 g_wohi[Dd*Dd], g_wolo[Dd*Dd];
static __device__ float g_qsc[Dd], g_qsh[Dd];
static __device__ float g_ksc[Dd], g_ksh[Dd];

// ======================= small helpers =======================
__device__ __forceinline__ uint32_t smem_u32(const void* p) {
    uint32_t a;
    asm("{ .reg .u64 t; cvta.to.shared.u64 t, %1; cvt.u32.u64 %0, t; }" : "=r"(a) : "l"(p));
    return a;
}
__device__ __forceinline__ uint32_t lds32(uint32_t a) {
    uint32_t v;
    asm volatile("ld.shared.b32 %0, [%1];" : "=r"(v) : "r"(a));
    return v;
}
__device__ __forceinline__ void cpasync16(uint32_t dst, const void* src) {
    asm volatile("cp.async.cg.shared.global [%0], [%1], 16;" :: "r"(dst), "l"(src));
}
#define CP_COMMIT() asm volatile("cp.async.commit_group;" ::: "memory")
#define CP_WAIT1()  asm volatile("cp.async.wait_group 1;" ::: "memory")

__device__ __forceinline__ void mma16816(float* c, const uint32_t* a, uint32_t b0, uint32_t b1) {
    asm volatile(
        "mma.sync.aligned.m16n8k16.row.col.f32.bf16.bf16.f32 "
        "{%0,%1,%2,%3}, {%4,%5,%6,%7}, {%8,%9}, {%0,%1,%2,%3};"
        : "+f"(c[0]), "+f"(c[1]), "+f"(c[2]), "+f"(c[3])
        : "r"(a[0]), "r"(a[1]), "r"(a[2]), "r"(a[3]), "r"(b0), "r"(b1));
}

// ======================= prep kernels =======================
__global__ void split_bf16(const float* __restrict__ x,
                           __nv_bfloat16* __restrict__ hi,
                           __nv_bfloat16* __restrict__ lo, int n)
{
    int i = (blockIdx.x * blockDim.x + threadIdx.x) * 4;
    if (i >= n) return;
    float4 v = *(const float4*)(x + i);
    __nv_bfloat16 h0 = __float2bfloat16(v.x);
    __nv_bfloat16 h1 = __float2bfloat16(v.y);
    __nv_bfloat16 h2 = __float2bfloat16(v.z);
    __nv_bfloat16 h3 = __float2bfloat16(v.w);
    __nv_bfloat16 l0 = __float2bfloat16(v.x - __bfloat162float(h0));
    __nv_bfloat16 l1 = __float2bfloat16(v.y - __bfloat162float(h1));
    __nv_bfloat16 l2 = __float2bfloat16(v.z - __bfloat162float(h2));
    __nv_bfloat16 l3 = __float2bfloat16(v.w - __bfloat162float(h3));
    uint2 oh, ol;
    oh.x = (uint32_t)__bfloat16_as_ushort(h0) | ((uint32_t)__bfloat16_as_ushort(h1) << 16);
    oh.y = (uint32_t)__bfloat16_as_ushort(h2) | ((uint32_t)__bfloat16_as_ushort(h3) << 16);
    ol.x = (uint32_t)__bfloat16_as_ushort(l0) | ((uint32_t)__bfloat16_as_ushort(l1) << 16);
    ol.y = (uint32_t)__bfloat16_as_ushort(l2) | ((uint32_t)__bfloat16_as_ushort(l3) << 16);
    *(uint2*)(hi + i) = oh;
    *(uint2*)(lo + i) = ol;
}

// conv weight [e][d][s] -> hi/lo [s][e][d]
__global__ void repack_conv_split(const float* __restrict__ W,
                                  __nv_bfloat16* __restrict__ hi,
                                  __nv_bfloat16* __restrict__ lo)
{
    int idx = blockIdx.x * blockDim.x + threadIdx.x;
    if (idx >= KSz * Dd * Dd) return;
    int s = idx / (Dd * Dd);
    int r = idx - s * Dd * Dd;       // r = e*Dd + d
    float v = W[(size_t)r * KSz + s];
    __nv_bfloat16 h = __float2bfloat16(v);
    hi[idx] = h;
    lo[idx] = __float2bfloat16(v - __bfloat162float(h));
}

__global__ void affine_k(const float* __restrict__ bc, const float* __restrict__ g,
                         const float* __restrict__ beta, const float* __restrict__ m,
                         const float* __restrict__ v, float* __restrict__ scale,
                         float* __restrict__ shift) {
    int e = blockIdx.x * blockDim.x + threadIdx.x;
    if (e >= Dd) return;
    float sc = g[e] * rsqrtf(v[e] + EPSv);
    scale[e] = sc;
    shift[e] = beta[e] + (bc[e] - m[e]) * sc;
}

// ======================= mma.sync GEMM =======================
// Out[(bt*128+m), e0+j] = affine( sum_s sum_d A[((bt+s-(nt-1))*128+m), d] * B[s][e0+j][d] )
// A,B pre-split bf16 hi/lo. 3-pass split hi*hi + hi*lo + lo*hi, fp32 accum in regs.
// CTA: 128(M) x 128(E); K stages of 32; 256 threads (8 warps of 32x64 tiles).
// smem tile: [128 rows][40 halves] (stride 80B, bank-conflict-free frag loads).
#define TILE_B  (128 * 80)            // 10240 B per bf16 tile
#define STAGE_B (4 * TILE_B)          // Ahi, Alo, Bhi, Blo
#define SMEM_G  (2 * STAGE_B)         // 81920 B

struct StageSrc { const __nv_bfloat16 *ah, *al, *bh, *bl; };

__device__ __forceinline__ void issue_stage(uint32_t sbuf, const StageSrc& s, int tid) {
#pragma unroll
    for (int j = 0; j < 2; ++j) {
        const int idx = tid + 256 * j;           // 0..511
        const int r   = idx >> 2;                // 0..127
        const int c16 = idx & 3;                 // 16B chunk within 32-half row
        const uint32_t doff = (uint32_t)(r * 80 + c16 * 16);
        const size_t  goff = (size_t)r * Dd + c16 * 8;
        cpasync16(sbuf +              doff, s.ah + goff);
        cpasync16(sbuf +     TILE_B + doff, s.al + goff);
        cpasync16(sbuf + 2 * TILE_B + doff, s.bh + goff);
        cpasync16(sbuf + 3 * TILE_B + doff, s.bl + goff);
    }
}

__global__ void __launch_bounds__(256, 2)
mma_gemm(const __nv_bfloat16* __restrict__ Ahi, const __nv_bfloat16* __restrict__ Alo,
         const __nv_bfloat16* __restrict__ Bhi, const __nv_bfloat16* __restrict__ Blo,
         int ntaps,
         const float* __restrict__ scale, const float* __restrict__ shift,
         float* __restrict__ Out)
{
    extern __shared__ __align__(16) char sm[];
    const uint32_t base_u = smem_u32(sm);

    const int tid = threadIdx.x;
    const int wid = tid >> 5;
    const int lane = tid & 31;
    const int qr = lane >> 2;       // 0..7
    const int qc = lane & 3;        // 0..3

    const int warp_m = (wid & 3) * 32;
    const int warp_n = (wid >> 2) * 64;

    const int e0 = blockIdx.x * 128;
    const int bt = blockIdx.y;
    const int t  = bt & (Tt - 1);

    // valid taps
    int taps[KSz]; int ntv = 0;
    for (int s = 0; s < ntaps; ++s)
        if (t - (ntaps - 1) + s >= 0) taps[ntv++] = s;
    const int ns = ntv * 16;        // stages (K=32 each)

    auto src_of = [&](int c) -> StageSrc {
        const int s  = taps[c >> 4];
        const int k0 = (c & 15) * 32;
        const size_t arow = (size_t)(bt - (ntaps - 1) + s) * 128;
        const size_t aoff = arow * Dd + k0;
        const size_t boff = (size_t)s * Dd * Dd + (size_t)e0 * Dd + k0;
        StageSrc r;
        r.ah = Ahi + aoff; r.al = Alo + aoff;
        r.bh = Bhi + boff; r.bl = Blo + boff;
        return r;
    };

    float acc[2][8][4];
#pragma unroll
    for (int i = 0; i < 2; ++i)
#pragma unroll
        for (int j = 0; j < 8; ++j)
#pragma unroll
            for (int q = 0; q < 4; ++q) acc[i][j][q] = 0.0f;

    // prologue: stages 0 and 1 in flight
    issue_stage(base_u, src_of(0), tid); CP_COMMIT();
    if (ns > 1) { issue_stage(base_u + STAGE_B, src_of(1), tid); }
    CP_COMMIT();

    const uint32_t a_base0 = (uint32_t)((warp_m + qr) * 80 + qc * 4);
    const uint32_t b_base0 = (uint32_t)((warp_n + qr) * 80 + qc * 4);

    for (int c = 0; c < ns; ++c) {
        CP_WAIT1();
        __syncthreads();

        const uint32_t sbuf = base_u + (uint32_t)(c & 1) * STAGE_B;
        const uint32_t Ah = sbuf, Al = sbuf + TILE_B, Bh = sbuf + 2 * TILE_B, Bl = sbuf + 3 * TILE_B;

#pragma unroll
        for (int kk = 0; kk < 2; ++kk) {
            const uint32_t kb = (uint32_t)(kk * 32);
            uint32_t ah[2][4], al[2][4];
#pragma unroll
            for (int mt = 0; mt < 2; ++mt) {
                const uint32_t ra = a_base0 + (uint32_t)(mt * 16 * 80) + kb;
                ah[mt][0] = lds32(Ah + ra);
                ah[mt][1] = lds32(Ah + ra + 8 * 80);
                ah[mt][2] = lds32(Ah + ra + 16);
                ah[mt][3] = lds32(Ah + ra + 8 * 80 + 16);
                al[mt][0] = lds32(Al + ra);
                al[mt][1] = lds32(Al + ra + 8 * 80);
                al[mt][2] = lds32(Al + ra + 16);
                al[mt][3] = lds32(Al + ra + 8 * 80 + 16);
            }
#pragma unroll
            for (int nt = 0; nt < 8; ++nt) {
                const uint32_t rb = b_base0 + (uint32_t)(nt * 8 * 80) + kb;
                const uint32_t bh0 = lds32(Bh + rb);
                const uint32_t bh1 = lds32(Bh + rb + 16);
                const uint32_t bl0 = lds32(Bl + rb);
                const uint32_t bl1 = lds32(Bl + rb + 16);
#pragma unroll
                for (int mt = 0; mt < 2; ++mt) {
                    mma16816(acc[mt][nt], ah[mt], bh0, bh1);   // hi*hi
                    mma16816(acc[mt][nt], ah[mt], bl0, bl1);   // hi*lo
                    mma16816(acc[mt][nt], al[mt], bh0, bh1);   // lo*hi
                }
            }
        }

        __syncthreads();
        if (c + 2 < ns) issue_stage(base_u + (uint32_t)(c & 1) * STAGE_B, src_of(c + 2), tid);
        CP_COMMIT();
    }

    // epilogue: affine + store (float2 per row pair)
#pragma unroll
    for (int mt = 0; mt < 2; ++mt) {
#pragma unroll
        for (int nt = 0; nt < 8; ++nt) {
            const int col = warp_n + nt * 8 + 2 * qc;
            const int e   = e0 + col;
            float s0 = scale ? scale[e]     : 1.0f;
            float s1 = scale ? scale[e + 1] : 1.0f;
            float h0 = shift ? shift[e]     : 0.0f;
            float h1 = shift ? shift[e + 1] : 0.0f;
            const int row0 = warp_m + mt * 16 + qr;
            float* p0 = Out + ((size_t)bt * 128 + row0) * Dd + e;
            float* p1 = Out + ((size_t)bt * 128 + row0 + 8) * Dd + e;
            float2 v0 = make_float2(acc[mt][nt][0] * s0 + h0, acc[mt][nt][1] * s1 + h1);
            float2 v1 = make_float2(acc[mt][nt][2] * s0 + h0, acc[mt][nt][3] * s1 + h1);
            *(float2*)p0 = v0;
            *(float2*)p1 = v1;
        }
    }
}

// ======================= attention (fp32) =======================
#define SMEM_ATTN ((64*68 + 64*68 + 64*64 + 64*65) * 4)

__global__ void __launch_bounds__(256) attn_kernel(
    const float* __restrict__ Q, const float* __restrict__ K,
    const float* __restrict__ V, float* __restrict__ O)
{
    extern __shared__ float smf[];
    float* Qs = smf;              // [64][68]
    float* Ks = Qs + 64 * 68;     // [64][68]
    float* Vs = Ks + 64 * 68;     // [64][64]
    float* At = Vs + 64 * 64;     // [64][65]

    const int blk = blockIdx.x;
    const int h = blk & (KHh - 1);
    const int n = (blk >> 3) & (Nn - 1);
    const int b = blk >> 10;

    const int tid = threadIdx.x;
    const int r  = tid >> 2;
    const int c0 = (tid & 3) * 16;

    const size_t tstride = (size_t)Nn * Dd;
    const size_t base = ((size_t)b * Tt * Nn + n) * Dd + h * DHh;

#pragma unroll
    for (int j = 0; j < 16; j += 4) {
        const size_t g = base + (size_t)r * tstride + c0 + j;
        *(float4*)&Qs[r * 68 + c0 + j] = *(const float4*)(Q + g);
        *(float4*)&Ks[r * 68 + c0 + j] = *(const float4*)(K + g);
        *(float4*)&Vs[r * 64 + c0 + j] = *(const float4*)(V + g);
    }
    __syncthreads();

    float acc[16];
#pragma unroll
    for (int p = 0; p < 16; ++p) acc[p] = 0.0f;
    for (int d = 0; d < 64; d += 4) {
        float4 qv = *(const float4*)&Qs[r * 68 + d];
#pragma unroll
        for (int pp = 0; pp < 16; ++pp) {
            float4 kv = *(const float4*)&Ks[(c0 + pp) * 68 + d];
            acc[pp] += qv.x * kv.x + qv.y * kv.y + qv.z * kv.z + qv.w * kv.w;
        }
    }

    float mx = -1e30f;
#pragma unroll
    for (int pp = 0; pp < 16; ++pp) { acc[pp] *= 0.125f; mx = fmaxf(mx, acc[pp]); }
    mx = fmaxf(mx, __shfl_xor_sync(0xffffffffu, mx, 1));
    mx = fmaxf(mx, __shfl_xor_sync(0xffffffffu, mx, 2));
    float sum = 0.0f;
#pragma unroll
    for (int pp = 0; pp < 16; ++pp) { acc[pp] = __expf(acc[pp] - mx); sum += acc[pp]; }
    sum += __shfl_xor_sync(0xffffffffu, sum, 1);
    sum += __shfl_xor_sync(0xffffffffu, sum, 2);
    const float inv = 1.0f / sum;
#pragma unroll
    for (int pp = 0; pp < 16; ++pp) At[r * 65 + c0 + pp] = acc[pp] * inv;
    __syncthreads();

    float o[16];
#pragma unroll
    for (int j = 0; j < 16; ++j) o[j] = 0.0f;
    for (int p = 0; p < 64; ++p) {
        const float av = At[r * 65 + p];
#pragma unroll
        for (int j4 = 0; j4 < 16; j4 += 4) {
            float4 vv = *(const float4*)&Vs[p * 64 + c0 + j4];
            o[j4 + 0] += av * vv.x;
            o[j4 + 1] += av * vv.y;
            o[j4 + 2] += av * vv.z;
            o[j4 + 3] += av * vv.w;
        }
    }
#pragma unroll
    for (int j4 = 0; j4 < 16; j4 += 4) {
        *(float4*)(O + base + (size_t)r * tstride + c0 + j4) =
            make_float4(o[j4], o[j4 + 1], o[j4 + 2], o[j4 + 3]);
    }
}

// ======================= launch =======================
extern "C" void kernel_launch(void* const* d_in, const int* in_sizes, int n_in,
                              void* d_out, int out_size)
{
    const float* X     = (const float*)d_in[0];
    const float* Wq    = (const float*)d_in[1];
    const float* bq    = (const float*)d_in[2];
    const float* gq    = (const float*)d_in[3];
    const float* betaq = (const float*)d_in[4];
    const float* mq    = (const float*)d_in[5];
    const float* vq    = (const float*)d_in[6];
    const float* Wk    = (const float*)d_in[7];
    const float* bk    = (const float*)d_in[8];
    const float* gk    = (const float*)d_in[9];
    const float* betak = (const float*)d_in[10];
    const float* mk    = (const float*)d_in[11];
    const float* vk    = (const float*)d_in[12];
    const float* Wv    = (const float*)d_in[13];
    const float* bv    = (const float*)d_in[14];
    const float* Wo    = (const float*)d_in[15];
    const float* bo    = (const float*)d_in[16];
    float* out = (float*)d_out;

    float *pQ, *pK, *pV, *pAO, *pqsc, *pqsh, *pksc, *pksh;
    __nv_bfloat16 *pXhi, *pXlo, *pAOhi, *pAOlo;
    __nv_bfloat16 *pwqh, *pwql, *pwkh, *pwkl, *pwvh, *pwvl, *pwoh, *pwol;
    cudaGetSymbolAddress((void**)&pQ,  g_Q);
    cudaGetSymbolAddress((void**)&pK,  g_K);
    cudaGetSymbolAddress((void**)&pV,  g_V);
    cudaGetSymbolAddress((void**)&pAO, g_AO);
    cudaGetSymbolAddress((void**)&pXhi, g_Xhi);
    cudaGetSymbolAddress((void**)&pXlo, g_Xlo);
    cudaGetSymbolAddress((void**)&pAOhi, g_AOhi);
    cudaGetSymbolAddress((void**)&pAOlo, g_AOlo);
    cudaGetSymbolAddress((void**)&pwqh, g_wqhi);
    cudaGetSymbolAddress((void**)&pwql, g_wqlo);
    cudaGetSymbolAddress((void**)&pwkh, g_wkhi);
    cudaGetSymbolAddress((void**)&pwkl, g_wklo);
    cudaGetSymbolAddress((void**)&pwvh, g_wvhi);
    cudaGetSymbolAddress((void**)&pwvl, g_wvlo);
    cudaGetSymbolAddress((void**)&pwoh, g_wohi);
    cudaGetSymbolAddress((void**)&pwol, g_wolo);
    cudaGetSymbolAddress((void**)&pqsc, g_qsc);
    cudaGetSymbolAddress((void**)&pqsh, g_qsh);
    cudaGetSymbolAddress((void**)&pksc, g_ksc);
    cudaGetSymbolAddress((void**)&pksh, g_ksh);

    cudaFuncSetAttribute(mma_gemm, cudaFuncAttributeMaxDynamicSharedMemorySize, SMEM_G);
    cudaFuncSetAttribute(attn_kernel, cudaFuncAttributeMaxDynamicSharedMemorySize, SMEM_ATTN);

    // prep
    split_bf16<<<NELEM/4/256, 256>>>(X, pXhi, pXlo, NELEM);
    repack_conv_split<<<(KSz*Dd*Dd + 255)/256, 256>>>(Wq, pwqh, pwql);
    repack_conv_split<<<(KSz*Dd*Dd + 255)/256, 256>>>(Wk, pwkh, pwkl);
    split_bf16<<<(Dd*Dd)/4/256, 256>>>(Wv, pwvh, pwvl, Dd*Dd);
    split_bf16<<<(Dd*Dd)/4/256, 256>>>(Wo, pwoh, pwol, Dd*Dd);
    affine_k<<<2, 256>>>(bq, gq, betaq, mq, vq, pqsc, pqsh);
    affine_k<<<2, 256>>>(bk, gk, betak, mk, vk, pksc, pksh);

    // GEMMs via mma.sync (bf16 3-pass)
    dim3 grid(Dd/128, Bb*Tt);
    mma_gemm<<<grid, 256, SMEM_G>>>(pXhi, pXlo, pwqh, pwql, KSz, pqsc, pqsh, pQ);
    mma_gemm<<<grid, 256, SMEM_G>>>(pXhi, pXlo, pwkh, pwkl, KSz, pksc, pksh, pK);
    mma_gemm<<<grid, 256, SMEM_G>>>(pXhi, pXlo, pwvh, pwvl, 1, nullptr, bv, pV);

    // attention (fp32)
    attn_kernel<<<Bb*Nn*KHh, 256, SMEM_ATTN>>>(pQ, pK, pV, pAO);

    // output projection
    split_bf16<<<NELEM/4/256, 256>>>(pAO, pAOhi, pAOlo, NELEM);
    mma_gemm<<<grid, 256, SMEM_G>>>(pAOhi, pAOlo, pwoh, pwol, 1, nullptr, bo, out);
}

// round 4
// speedup vs baseline: 2.7667x; 1.2283x over previous
#include <cuda_runtime.h>
#include <cuda_fp16.h>
#include <cstdint>
#include <math.h>

#define Bb 8
#define Tt 64
#define Nn 128
#define Dd 512
#define KHh 8
#define DHh 64
#define KSz 3
#define EPSv 1e-5f

#define NELEM (Bb*Tt*Nn*Dd)   // 16,777,216

// weight prescale: weights stored *2^10 so fp16 lo-split stays normal;
// epilogue multiplies accumulators by 2^-10.
#define WSCALE 1024.0f
#define WISCALE 0.0009765625f

// ======================= device scratch =======================
static __device__ float g_Q[NELEM];
static __device__ float g_K[NELEM];
static __device__ float g_V[NELEM];
static __device__ float g_AO[NELEM];
static __device__ __half g_Xh[NELEM];
static __device__ __half g_AOh[NELEM];
static __device__ __half g_wqh[KSz*Dd*Dd], g_wql[KSz*Dd*Dd];
static __device__ __half g_wkh[KSz*Dd*Dd], g_wkl[KSz*Dd*Dd];
static __device__ __half g_wvh[Dd*Dd], g_wvl[Dd*Dd];
static __device__ __half g_woh[Dd*Dd], g_wol[Dd*Dd];
static __device__ float g_qsc[Dd], g_qsh[Dd];
static __device__ float g_ksc[Dd], g_ksh[Dd];

// ======================= small helpers =======================
__device__ __forceinline__ uint32_t smem_u32(const void* p) {
    uint32_t a;
    asm("{ .reg .u64 t; cvta.to.shared.u64 t, %1; cvt.u32.u64 %0, t; }" : "=r"(a) : "l"(p));
    return a;
}
__device__ __forceinline__ uint32_t lds32(uint32_t a) {
    uint32_t v;
    asm volatile("ld.shared.b32 %0, [%1];" : "=r"(v) : "r"(a));
    return v;
}
__device__ __forceinline__ void cpasync16(uint32_t dst, const void* src) {
    asm volatile("cp.async.cg.shared.global [%0], [%1], 16;" :: "r"(dst), "l"(src));
}
#define CP_COMMIT() asm volatile("cp.async.commit_group;" ::: "memory")
#define CP_WAIT1()  asm volatile("cp.async.wait_group 1;" ::: "memory")

__device__ __forceinline__ void mma16816h(float* c, const uint32_t* a, uint32_t b0, uint32_t b1) {
    asm volatile(
        "mma.sync.aligned.m16n8k16.row.col.f32.f16.f16.f32 "
        "{%0,%1,%2,%3}, {%4,%5,%6,%7}, {%8,%9}, {%0,%1,%2,%3};"
        : "+f"(c[0]), "+f"(c[1]), "+f"(c[2]), "+f"(c[3])
        : "r"(a[0]), "r"(a[1]), "r"(a[2]), "r"(a[3]), "r"(b0), "r"(b1));
}

// ======================= prep kernels =======================
// fp32 -> fp16 (single), layout preserved
__global__ void to_fp16(const float* __restrict__ x, __half* __restrict__ y, int n)
{
    int i = (blockIdx.x * blockDim.x + threadIdx.x) * 4;
    if (i >= n) return;
    float4 v = *(const float4*)(x + i);
    __half2 a = __floats2half2_rn(v.x, v.y);
    __half2 b = __floats2half2_rn(v.z, v.w);
    uint2 o;
    o.x = *(const uint32_t*)&a;
    o.y = *(const uint32_t*)&b;
    *(uint2*)(y + i) = o;
}

// conv weight [e][d][s] -> hi/lo fp16 [s][e][d], *WSCALE
__global__ void repack_conv_h(const float* __restrict__ W,
                              __half* __restrict__ hi, __half* __restrict__ lo)
{
    int idx = blockIdx.x * blockDim.x + threadIdx.x;
    if (idx >= KSz * Dd * Dd) return;
    int s = idx / (Dd * Dd);
    int r = idx - s * Dd * Dd;       // r = e*Dd + d
    float v = W[(size_t)r * KSz + s] * WSCALE;
    __half h = __float2half_rn(v);
    hi[idx] = h;
    lo[idx] = __float2half_rn(v - __half2float(h));
}

// fc weight [e][d] -> hi/lo fp16 same layout (already K-contiguous), *WSCALE
__global__ void split_fc_h(const float* __restrict__ W,
                           __half* __restrict__ hi, __half* __restrict__ lo, int n)
{
    int i = blockIdx.x * blockDim.x + threadIdx.x;
    if (i >= n) return;
    float v = W[i] * WSCALE;
    __half h = __float2half_rn(v);
    hi[i] = h;
    lo[i] = __float2half_rn(v - __half2float(h));
}

__global__ void affine_k(const float* __restrict__ bc, const float* __restrict__ g,
                         const float* __restrict__ beta, const float* __restrict__ m,
                         const float* __restrict__ v, float* __restrict__ scale,
                         float* __restrict__ shift) {
    int e = blockIdx.x * blockDim.x + threadIdx.x;
    if (e >= Dd) return;
    float sc = g[e] * rsqrtf(v[e] + EPSv);
    scale[e] = sc;
    shift[e] = beta[e] + (bc[e] - m[e]) * sc;
}

// ======================= mma.sync GEMM (fp16 2-pass) =======================
// Out[(bt*128+m), e0+j] = affine( WISCALE * sum_s sum_d A[..., d] * Wscaled[s][e0+j][d] )
// A single fp16; B split hi/lo fp16 (prescaled). acc = A*Bh + A*Bl in fp32.
// CTA: 128(M) x 128(E); K stages of 32; 256 threads (8 warps of 32x64 tiles).
// smem tile: [128 rows][stride 80B] conflict-free.
#define TILE_B  (128 * 80)            // 10240 B per fp16 tile
#define STAGE_B (3 * TILE_B)          // A, Bhi, Blo
#define SMEM_G  (2 * STAGE_B)         // 61440 B

struct StageSrc { const __half *a, *bh, *bl; };

__device__ __forceinline__ void issue_stage(uint32_t sbuf, const StageSrc& s, int tid) {
#pragma unroll
    for (int j = 0; j < 2; ++j) {
        const int idx = tid + 256 * j;           // 0..511
        const int r   = idx >> 2;                // 0..127
        const int c16 = idx & 3;                 // 16B chunk
        const uint32_t doff = (uint32_t)(r * 80 + c16 * 16);
        const size_t  goff = (size_t)r * Dd + c16 * 8;
        cpasync16(sbuf +              doff, s.a  + goff);
        cpasync16(sbuf +     TILE_B + doff, s.bh + goff);
        cpasync16(sbuf + 2 * TILE_B + doff, s.bl + goff);
    }
}

__global__ void __launch_bounds__(256, 2)
mma_gemm(const __half* __restrict__ A,
         const __half* __restrict__ Bhi, const __half* __restrict__ Blo,
         int ntaps,
         const float* __restrict__ scale, const float* __restrict__ shift,
         float* __restrict__ Out)
{
    extern __shared__ __align__(16) char sm[];
    const uint32_t base_u = smem_u32(sm);

    const int tid = threadIdx.x;
    const int wid = tid >> 5;
    const int lane = tid & 31;
    const int qr = lane >> 2;       // 0..7
    const int qc = lane & 3;        // 0..3

    const int warp_m = (wid & 3) * 32;
    const int warp_n = (wid >> 2) * 64;

    const int e0 = blockIdx.x * 128;
    const int bt = blockIdx.y;
    const int t  = bt & (Tt - 1);

    int taps[KSz]; int ntv = 0;
    for (int s = 0; s < ntaps; ++s)
        if (t - (ntaps - 1) + s >= 0) taps[ntv++] = s;
    const int ns = ntv * 16;        // K=32 stages

    auto src_of = [&](int c) -> StageSrc {
        const int s  = taps[c >> 4];
        const int k0 = (c & 15) * 32;
        const size_t arow = (size_t)(bt - (ntaps - 1) + s) * 128;
        StageSrc r;
        r.a  = A + arow * Dd + k0;
        const size_t boff = (size_t)s * Dd * Dd + (size_t)e0 * Dd + k0;
        r.bh = Bhi + boff; r.bl = Blo + boff;
        return r;
    };

    float acc[2][8][4];
#pragma unroll
    for (int i = 0; i < 2; ++i)
#pragma unroll
        for (int j = 0; j < 8; ++j)
#pragma unroll
            for (int q = 0; q < 4; ++q) acc[i][j][q] = 0.0f;

    issue_stage(base_u, src_of(0), tid); CP_COMMIT();
    if (ns > 1) { issue_stage(base_u + STAGE_B, src_of(1), tid); }
    CP_COMMIT();

    const uint32_t a_base0 = (uint32_t)((warp_m + qr) * 80 + qc * 4);
    const uint32_t b_base0 = (uint32_t)((warp_n + qr) * 80 + qc * 4);

    for (int c = 0; c < ns; ++c) {
        CP_WAIT1();
        __syncthreads();

        const uint32_t sbuf = base_u + (uint32_t)(c & 1) * STAGE_B;
        const uint32_t Ab = sbuf, Bh = sbuf + TILE_B, Bl = sbuf + 2 * TILE_B;

#pragma unroll
        for (int kk = 0; kk < 2; ++kk) {
            const uint32_t kb = (uint32_t)(kk * 32);
            uint32_t ah[2][4];
#pragma unroll
            for (int mt = 0; mt < 2; ++mt) {
                const uint32_t ra = a_base0 + (uint32_t)(mt * 16 * 80) + kb;
                ah[mt][0] = lds32(Ab + ra);
                ah[mt][1] = lds32(Ab + ra + 8 * 80);
                ah[mt][2] = lds32(Ab + ra + 16);
                ah[mt][3] = lds32(Ab + ra + 8 * 80 + 16);
            }
#pragma unroll
            for (int nt = 0; nt < 8; ++nt) {
                const uint32_t rb = b_base0 + (uint32_t)(nt * 8 * 80) + kb;
                const uint32_t bh0 = lds32(Bh + rb);
                const uint32_t bh1 = lds32(Bh + rb + 16);
                const uint32_t bl0 = lds32(Bl + rb);
                const uint32_t bl1 = lds32(Bl + rb + 16);
#pragma unroll
                for (int mt = 0; mt < 2; ++mt) {
                    mma16816h(acc[mt][nt], ah[mt], bh0, bh1);   // A * B_hi
                    mma16816h(acc[mt][nt], ah[mt], bl0, bl1);   // A * B_lo
                }
            }
        }

        __syncthreads();
        if (c + 2 < ns) issue_stage(base_u + (uint32_t)(c & 1) * STAGE_B, src_of(c + 2), tid);
        CP_COMMIT();
    }

    // epilogue: un-prescale, affine, store
#pragma unroll
    for (int mt = 0; mt < 2; ++mt) {
#pragma unroll
        for (int nt = 0; nt < 8; ++nt) {
            const int col = warp_n + nt * 8 + 2 * qc;
            const int e   = e0 + col;
            float s0 = (scale ? scale[e]     : 1.0f) * WISCALE;
            float s1 = (scale ? scale[e + 1] : 1.0f) * WISCALE;
            float h0 = shift ? shift[e]     : 0.0f;
            float h1 = shift ? shift[e + 1] : 0.0f;
            const int row0 = warp_m + mt * 16 + qr;
            float* p0 = Out + ((size_t)bt * 128 + row0) * Dd + e;
            float* p1 = Out + ((size_t)bt * 128 + row0 + 8) * Dd + e;
            *(float2*)p0 = make_float2(acc[mt][nt][0] * s0 + h0, acc[mt][nt][1] * s1 + h1);
            *(float2*)p1 = make_float2(acc[mt][nt][2] * s0 + h0, acc[mt][nt][3] * s1 + h1);
        }
    }
}

// ======================= attention (fp32) =======================
#define SMEM_ATTN ((64*68 + 64*68 + 64*64 + 64*65) * 4)

__global__ void __launch_bounds__(256) attn_kernel(
    const float* __restrict__ Q, const float* __restrict__ K,
    const float* __restrict__ V, float* __restrict__ O)
{
    extern __shared__ float smf[];
    float* Qs = smf;              // [64][68]
    float* Ks = Qs + 64 * 68;     // [64][68]
    float* Vs = Ks + 64 * 68;     // [64][64]
    float* At = Vs + 64 * 64;     // [64][65]

    const int blk = blockIdx.x;
    const int h = blk & (KHh - 1);
    const int n = (blk >> 3) & (Nn - 1);
    const int b = blk >> 10;

    const int tid = threadIdx.x;
    const int r  = tid >> 2;
    const int c0 = (tid & 3) * 16;

    const size_t tstride = (size_t)Nn * Dd;
    const size_t base = ((size_t)b * Tt * Nn + n) * Dd + h * DHh;

#pragma unroll
    for (int j = 0; j < 16; j += 4) {
        const size_t g = base + (size_t)r * tstride + c0 + j;
        *(float4*)&Qs[r * 68 + c0 + j] = *(const float4*)(Q + g);
        *(float4*)&Ks[r * 68 + c0 + j] = *(const float4*)(K + g);
        *(float4*)&Vs[r * 64 + c0 + j] = *(const float4*)(V + g);
    }
    __syncthreads();

    float acc[16];
#pragma unroll
    for (int p = 0; p < 16; ++p) acc[p] = 0.0f;
    for (int d = 0; d < 64; d += 4) {
        float4 qv = *(const float4*)&Qs[r * 68 + d];
#pragma unroll
        for (int pp = 0; pp < 16; ++pp) {
            float4 kv = *(const float4*)&Ks[(c0 + pp) * 68 + d];
            acc[pp] += qv.x * kv.x + qv.y * kv.y + qv.z * kv.z + qv.w * kv.w;
        }
    }

    float mx = -1e30f;
#pragma unroll
    for (int pp = 0; pp < 16; ++pp) { acc[pp] *= 0.125f; mx = fmaxf(mx, acc[pp]); }
    mx = fmaxf(mx, __shfl_xor_sync(0xffffffffu, mx, 1));
    mx = fmaxf(mx, __shfl_xor_sync(0xffffffffu, mx, 2));
    float sum = 0.0f;
#pragma unroll
    for (int pp = 0; pp < 16; ++pp) { acc[pp] = __expf(acc[pp] - mx); sum += acc[pp]; }
    sum += __shfl_xor_sync(0xffffffffu, sum, 1);
    sum += __shfl_xor_sync(0xffffffffu, sum, 2);
    const float inv = 1.0f / sum;
#pragma unroll
    for (int pp = 0; pp < 16; ++pp) At[r * 65 + c0 + pp] = acc[pp] * inv;
    __syncthreads();

    float o[16];
#pragma unroll
    for (int j = 0; j < 16; ++j) o[j] = 0.0f;
    for (int p = 0; p < 64; ++p) {
        const float av = At[r * 65 + p];
#pragma unroll
        for (int j4 = 0; j4 < 16; j4 += 4) {
            float4 vv = *(const float4*)&Vs[p * 64 + c0 + j4];
            o[j4 + 0] += av * vv.x;
            o[j4 + 1] += av * vv.y;
            o[j4 + 2] += av * vv.z;
            o[j4 + 3] += av * vv.w;
        }
    }
#pragma unroll
    for (int j4 = 0; j4 < 16; j4 += 4) {
        *(float4*)(O + base + (size_t)r * tstride + c0 + j4) =
            make_float4(o[j4], o[j4 + 1], o[j4 + 2], o[j4 + 3]);
    }
}

// ======================= launch =======================
extern "C" void kernel_launch(void* const* d_in, const int* in_sizes, int n_in,
                              void* d_out, int out_size)
{
    const float* X     = (const float*)d_in[0];
    const float* Wq    = (const float*)d_in[1];
    const float* bq    = (const float*)d_in[2];
    const float* gq    = (const float*)d_in[3];
    const float* betaq = (const float*)d_in[4];
    const float* mq    = (const float*)d_in[5];
    const float* vq    = (const float*)d_in[6];
    const float* Wk    = (const float*)d_in[7];
    const float* bk    = (const float*)d_in[8];
    const float* gk    = (const float*)d_in[9];
    const float* betak = (const float*)d_in[10];
    const float* mk    = (const float*)d_in[11];
    const float* vk    = (const float*)d_in[12];
    const float* Wv    = (const float*)d_in[13];
    const float* bv    = (const float*)d_in[14];
    const float* Wo    = (const float*)d_in[15];
    const float* bo    = (const float*)d_in[16];
    float* out = (float*)d_out;

    float *pQ, *pK, *pV, *pAO, *pqsc, *pqsh, *pksc, *pksh;
    __half *pXh, *pAOh;
    __half *pwqh, *pwql, *pwkh, *pwkl, *pwvh, *pwvl, *pwoh, *pwol;
    cudaGetSymbolAddress((void**)&pQ,  g_Q);
    cudaGetSymbolAddress((void**)&pK,  g_K);
    cudaGetSymbolAddress((void**)&pV,  g_V);
    cudaGetSymbolAddress((void**)&pAO, g_AO);
    cudaGetSymbolAddress((void**)&pXh, g_Xh);
    cudaGetSymbolAddress((void**)&pAOh, g_AOh);
    cudaGetSymbolAddress((void**)&pwqh, g_wqh);
    cudaGetSymbolAddress((void**)&pwql, g_wql);
    cudaGetSymbolAddress((void**)&pwkh, g_wkh);
    cudaGetSymbolAddress((void**)&pwkl, g_wkl);
    cudaGetSymbolAddress((void**)&pwvh, g_wvh);
    cudaGetSymbolAddress((void**)&pwvl, g_wvl);
    cudaGetSymbolAddress((void**)&pwoh, g_woh);
    cudaGetSymbolAddress((void**)&pwol, g_wol);
    cudaGetSymbolAddress((void**)&pqsc, g_qsc);
    cudaGetSymbolAddress((void**)&pqsh, g_qsh);
    cudaGetSymbolAddress((void**)&pksc, g_ksc);
    cudaGetSymbolAddress((void**)&pksh, g_ksh);

    cudaFuncSetAttribute(mma_gemm, cudaFuncAttributeMaxDynamicSharedMemorySize, SMEM_G);
    cudaFuncSetAttribute(attn_kernel, cudaFuncAttributeMaxDynamicSharedMemorySize, SMEM_ATTN);

    // prep
    to_fp16<<<NELEM/4/256, 256>>>(X, pXh, NELEM);
    repack_conv_h<<<(KSz*Dd*Dd + 255)/256, 256>>>(Wq, pwqh, pwql);
    repack_conv_h<<<(KSz*Dd*Dd + 255)/256, 256>>>(Wk, pwkh, pwkl);
    split_fc_h<<<(Dd*Dd + 255)/256, 256>>>(Wv, pwvh, pwvl, Dd*Dd);
    split_fc_h<<<(Dd*Dd + 255)/256, 256>>>(Wo, pwoh, pwol, Dd*Dd);
    affine_k<<<2, 256>>>(bq, gq, betaq, mq, vq, pqsc, pqsh);
    affine_k<<<2, 256>>>(bk, gk, betak, mk, vk, pksc, pksh);

    // GEMMs via mma.sync (fp16 2-pass)
    dim3 grid(Dd/128, Bb*Tt);
    mma_gemm<<<grid, 256, SMEM_G>>>(pXh, pwqh, pwql, KSz, pqsc, pqsh, pQ);
    mma_gemm<<<grid, 256, SMEM_G>>>(pXh, pwkh, pwkl, KSz, pksc, pksh, pK);
    mma_gemm<<<grid, 256, SMEM_G>>>(pXh, pwvh, pwvl, 1, nullptr, bv, pV);

    // attention (fp32)
    attn_kernel<<<Bb*Nn*KHh, 256, SMEM_ATTN>>>(pQ, pK, pV, pAO);

    // output projection
    to_fp16<<<NELEM/4/256, 256>>>(pAO, pAOh, NELEM);
    mma_gemm<<<grid, 256, SMEM_G>>>(pAOh, pwoh, pwol, 1, nullptr, bo, out);
}

// round 5
// speedup vs baseline: 3.3614x; 1.2150x over previous
#include <cuda_runtime.h>
#include <cuda_fp16.h>
#include <cstdint>
#include <math.h>

#define Bb 8
#define Tt 64
#define Nn 128
#define Dd 512
#define KHh 8
#define DHh 64
#define KSz 3
#define EPSv 1e-5f

#define NELEM (Bb*Tt*Nn*Dd)   // 16,777,216

// weight prescale: weights stored *2^10 keeps tiny weights out of fp16
// subnormal range; epilogue multiplies accumulators by 2^-10.
#define WSCALE 1024.0f
#define WISCALE 0.0009765625f

// ======================= device scratch =======================
static __device__ float g_Q[NELEM];
static __device__ float g_K[NELEM];
static __device__ float g_V[NELEM];
static __device__ __half g_Xh[NELEM];
static __device__ __half g_AOh[NELEM];
static __device__ __half g_wqh[KSz*Dd*Dd];
static __device__ __half g_wkh[KSz*Dd*Dd];
static __device__ __half g_wvh[Dd*Dd];
static __device__ __half g_woh[Dd*Dd];
static __device__ float g_qsc[Dd], g_qsh[Dd];
static __device__ float g_ksc[Dd], g_ksh[Dd];

// ======================= small helpers =======================
__device__ __forceinline__ uint32_t smem_u32(const void* p) {
    uint32_t a;
    asm("{ .reg .u64 t; cvta.to.shared.u64 t, %1; cvt.u32.u64 %0, t; }" : "=r"(a) : "l"(p));
    return a;
}
__device__ __forceinline__ uint32_t lds32(uint32_t a) {
    uint32_t v;
    asm volatile("ld.shared.b32 %0, [%1];" : "=r"(v) : "r"(a));
    return v;
}
__device__ __forceinline__ void cpasync16(uint32_t dst, const void* src) {
    asm volatile("cp.async.cg.shared.global [%0], [%1], 16;" :: "r"(dst), "l"(src));
}
#define CP_COMMIT() asm volatile("cp.async.commit_group;" ::: "memory")
#define CP_WAIT1()  asm volatile("cp.async.wait_group 1;" ::: "memory")

__device__ __forceinline__ void mma16816h(float* c, const uint32_t* a, uint32_t b0, uint32_t b1) {
    asm volatile(
        "mma.sync.aligned.m16n8k16.row.col.f32.f16.f16.f32 "
        "{%0,%1,%2,%3}, {%4,%5,%6,%7}, {%8,%9}, {%0,%1,%2,%3};"
        : "+f"(c[0]), "+f"(c[1]), "+f"(c[2]), "+f"(c[3])
        : "r"(a[0]), "r"(a[1]), "r"(a[2]), "r"(a[3]), "r"(b0), "r"(b1));
}

// ======================= prep kernels =======================
// fp32 -> fp16, layout preserved (no scaling)
__global__ void to_fp16(const float* __restrict__ x, __half* __restrict__ y, int n)
{
    int i = (blockIdx.x * blockDim.x + threadIdx.x) * 4;
    if (i >= n) return;
    float4 v = *(const float4*)(x + i);
    __half2 a = __floats2half2_rn(v.x, v.y);
    __half2 b = __floats2half2_rn(v.z, v.w);
    uint2 o;
    o.x = *(const uint32_t*)&a;
    o.y = *(const uint32_t*)&b;
    *(uint2*)(y + i) = o;
}

// fp32 -> fp16 * WSCALE, layout preserved (fc weights: already [e][d])
__global__ void to_fp16_ws(const float* __restrict__ x, __half* __restrict__ y, int n)
{
    int i = (blockIdx.x * blockDim.x + threadIdx.x) * 4;
    if (i >= n) return;
    float4 v = *(const float4*)(x + i);
    __half2 a = __floats2half2_rn(v.x * WSCALE, v.y * WSCALE);
    __half2 b = __floats2half2_rn(v.z * WSCALE, v.w * WSCALE);
    uint2 o;
    o.x = *(const uint32_t*)&a;
    o.y = *(const uint32_t*)&b;
    *(uint2*)(y + i) = o;
}

// conv weight [e][d][s] -> fp16 [s][e][d], *WSCALE
__global__ void repack_conv_h(const float* __restrict__ W, __half* __restrict__ out)
{
    int idx = blockIdx.x * blockDim.x + threadIdx.x;
    if (idx >= KSz * Dd * Dd) return;
    int s = idx / (Dd * Dd);
    int r = idx - s * Dd * Dd;       // r = e*Dd + d
    out[idx] = __float2half_rn(W[(size_t)r * KSz + s] * WSCALE);
}

__global__ void affine_k(const float* __restrict__ bc, const float* __restrict__ g,
                         const float* __restrict__ beta, const float* __restrict__ m,
                         const float* __restrict__ v, float* __restrict__ scale,
                         float* __restrict__ shift) {
    int e = blockIdx.x * blockDim.x + threadIdx.x;
    if (e >= Dd) return;
    float sc = g[e] * rsqrtf(v[e] + EPSv);
    scale[e] = sc;
    shift[e] = beta[e] + (bc[e] - m[e]) * sc;
}

// ======================= mma.sync GEMM (fp16 single-pass) =======================
// Out[(bt*128+m), e0+j] = affine( WISCALE * sum_s sum_d A[...,d] * Wscaled[s][e0+j][d] )
// CTA: 128(M) x 128(E); K stages of 32; 256 threads (8 warps, 32x64 warp tiles).
// smem tile: [128 rows][stride 80B], conflict-free fragment loads.
// 3-stage cp.async pipeline, loads issued before compute each iteration.
#define TILE_B  (128 * 80)            // 10240 B per fp16 tile
#define STAGE_B (2 * TILE_B)          // A, B
#define SMEM_G  (3 * STAGE_B)         // 61440 B

struct StageSrc { const __half *a, *b; };

__device__ __forceinline__ void issue_stage(uint32_t sbuf, const StageSrc& s, int tid) {
#pragma unroll
    for (int j = 0; j < 2; ++j) {
        const int idx = tid + 256 * j;           // 0..511
        const int r   = idx >> 2;                // 0..127
        const int c16 = idx & 3;                 // 16B chunk
        const uint32_t doff = (uint32_t)(r * 80 + c16 * 16);
        const size_t  goff = (size_t)r * Dd + c16 * 8;
        cpasync16(sbuf +          doff, s.a + goff);
        cpasync16(sbuf + TILE_B + doff, s.b + goff);
    }
}

__global__ void __launch_bounds__(256, 2)
mma_gemm(const __half* __restrict__ A, const __half* __restrict__ B,
         int ntaps,
         const float* __restrict__ scale, const float* __restrict__ shift,
         float* __restrict__ Out)
{
    extern __shared__ __align__(16) char sm[];
    const uint32_t base_u = smem_u32(sm);

    const int tid = threadIdx.x;
    const int wid = tid >> 5;
    const int lane = tid & 31;
    const int qr = lane >> 2;       // 0..7
    const int qc = lane & 3;        // 0..3

    const int warp_m = (wid & 3) * 32;
    const int warp_n = (wid >> 2) * 64;

    const int e0 = blockIdx.x * 128;
    const int bt = blockIdx.y;
    const int t  = bt & (Tt - 1);

    int taps[KSz]; int ntv = 0;
    for (int s = 0; s < ntaps; ++s)
        if (t - (ntaps - 1) + s >= 0) taps[ntv++] = s;
    const int ns = ntv * 16;        // K=32 stages

    auto src_of = [&](int c) -> StageSrc {
        const int s  = taps[c >> 4];
        const int k0 = (c & 15) * 32;
        const size_t arow = (size_t)(bt - (ntaps - 1) + s) * 128;
        StageSrc r;
        r.a = A + arow * Dd + k0;
        r.b = B + (size_t)s * Dd * Dd + (size_t)e0 * Dd + k0;
        return r;
    };

    float acc[2][8][4];
#pragma unroll
    for (int i = 0; i < 2; ++i)
#pragma unroll
        for (int j = 0; j < 8; ++j)
#pragma unroll
            for (int q = 0; q < 4; ++q) acc[i][j][q] = 0.0f;

    // prologue: stages 0 and 1 in flight
    issue_stage(base_u, src_of(0), tid); CP_COMMIT();
    if (ns > 1) issue_stage(base_u + STAGE_B, src_of(1), tid);
    CP_COMMIT();

    const uint32_t a_base0 = (uint32_t)((warp_m + qr) * 80 + qc * 4);
    const uint32_t b_base0 = (uint32_t)((warp_n + qr) * 80 + qc * 4);

    int buf = 0;                      // c % 3
    for (int c = 0; c < ns; ++c) {
        CP_WAIT1();                   // stage c resident
        __syncthreads();              // all threads done reading buf (c+2)%3 (from c-1's compute)

        // issue stage c+2 into buf (c+2)%3 BEFORE computing — overlaps loads with MMAs
        int buf2 = buf + 2; if (buf2 >= 3) buf2 -= 3;
        if (c + 2 < ns) issue_stage(base_u + (uint32_t)buf2 * STAGE_B, src_of(c + 2), tid);
        CP_COMMIT();

        const uint32_t sbuf = base_u + (uint32_t)buf * STAGE_B;
        const uint32_t Ab = sbuf, Bbs = sbuf + TILE_B;

#pragma unroll
        for (int kk = 0; kk < 2; ++kk) {
            const uint32_t kb = (uint32_t)(kk * 32);
            uint32_t ah[2][4];
#pragma unroll
            for (int mt = 0; mt < 2; ++mt) {
                const uint32_t ra = a_base0 + (uint32_t)(mt * 16 * 80) + kb;
                ah[mt][0] = lds32(Ab + ra);
                ah[mt][1] = lds32(Ab + ra + 8 * 80);
                ah[mt][2] = lds32(Ab + ra + 16);
                ah[mt][3] = lds32(Ab + ra + 8 * 80 + 16);
            }
#pragma unroll
            for (int nt = 0; nt < 8; ++nt) {
                const uint32_t rb = b_base0 + (uint32_t)(nt * 8 * 80) + kb;
                const uint32_t b0 = lds32(Bbs + rb);
                const uint32_t b1 = lds32(Bbs + rb + 16);
#pragma unroll
                for (int mt = 0; mt < 2; ++mt)
                    mma16816h(acc[mt][nt], ah[mt], b0, b1);
            }
        }

        if (++buf >= 3) buf -= 3;
    }

    // epilogue: un-prescale, affine, store
#pragma unroll
    for (int mt = 0; mt < 2; ++mt) {
#pragma unroll
        for (int nt = 0; nt < 8; ++nt) {
            const int col = warp_n + nt * 8 + 2 * qc;
            const int e   = e0 + col;
            float s0 = (scale ? scale[e]     : 1.0f) * WISCALE;
            float s1 = (scale ? scale[e + 1] : 1.0f) * WISCALE;
            float h0 = shift ? shift[e]     : 0.0f;
            float h1 = shift ? shift[e + 1] : 0.0f;
            const int row0 = warp_m + mt * 16 + qr;
            float* p0 = Out + ((size_t)bt * 128 + row0) * Dd + e;
            float* p1 = Out + ((size_t)bt * 128 + row0 + 8) * Dd + e;
            *(float2*)p0 = make_float2(acc[mt][nt][0] * s0 + h0, acc[mt][nt][1] * s1 + h1);
            *(float2*)p1 = make_float2(acc[mt][nt][2] * s0 + h0, acc[mt][nt][3] * s1 + h1);
        }
    }
}

// ======================= attention (fp32 compute, fp16 output) =======================
#define SMEM_ATTN ((64*68 + 64*68 + 64*64 + 64*65) * 4)

__global__ void __launch_bounds__(256) attn_kernel(
    const float* __restrict__ Q, const float* __restrict__ K,
    const float* __restrict__ V, __half* __restrict__ O)
{
    extern __shared__ float smf[];
    float* Qs = smf;              // [64][68]
    float* Ks = Qs + 64 * 68;     // [64][68]
    float* Vs = Ks + 64 * 68;     // [64][64]
    float* At = Vs + 64 * 64;     // [64][65]

    const int blk = blockIdx.x;
    const int h = blk & (KHh - 1);
    const int n = (blk >> 3) & (Nn - 1);
    const int b = blk >> 10;

    const int tid = threadIdx.x;
    const int r  = tid >> 2;
    const int c0 = (tid & 3) * 16;

    const size_t tstride = (size_t)Nn * Dd;
    const size_t base = ((size_t)b * Tt * Nn + n) * Dd + h * DHh;

#pragma unroll
    for (int j = 0; j < 16; j += 4) {
        const size_t g = base + (size_t)r * tstride + c0 + j;
        *(float4*)&Qs[r * 68 + c0 + j] = *(const float4*)(Q + g);
        *(float4*)&Ks[r * 68 + c0 + j] = *(const float4*)(K + g);
        *(float4*)&Vs[r * 64 + c0 + j] = *(const float4*)(V + g);
    }
    __syncthreads();

    float acc[16];
#pragma unroll
    for (int p = 0; p < 16; ++p) acc[p] = 0.0f;
    for (int d = 0; d < 64; d += 4) {
        float4 qv = *(const float4*)&Qs[r * 68 + d];
#pragma unroll
        for (int pp = 0; pp < 16; ++pp) {
            float4 kv = *(const float4*)&Ks[(c0 + pp) * 68 + d];
            acc[pp] += qv.x * kv.x + qv.y * kv.y + qv.z * kv.z + qv.w * kv.w;
        }
    }

    float mx = -1e30f;
#pragma unroll
    for (int pp = 0; pp < 16; ++pp) { acc[pp] *= 0.125f; mx = fmaxf(mx, acc[pp]); }
    mx = fmaxf(mx, __shfl_xor_sync(0xffffffffu, mx, 1));
    mx = fmaxf(mx, __shfl_xor_sync(0xffffffffu, mx, 2));
    float sum = 0.0f;
#pragma unroll
    for (int pp = 0; pp < 16; ++pp) { acc[pp] = __expf(acc[pp] - mx); sum += acc[pp]; }
    sum += __shfl_xor_sync(0xffffffffu, sum, 1);
    sum += __shfl_xor_sync(0xffffffffu, sum, 2);
    const float inv = 1.0f / sum;
#pragma unroll
    for (int pp = 0; pp < 16; ++pp) At[r * 65 + c0 + pp] = acc[pp] * inv;
    __syncthreads();

    float o[16];
#pragma unroll
    for (int j = 0; j < 16; ++j) o[j] = 0.0f;
    for (int p = 0; p < 64; ++p) {
        const float av = At[r * 65 + p];
#pragma unroll
        for (int j4 = 0; j4 < 16; j4 += 4) {
            float4 vv = *(const float4*)&Vs[p * 64 + c0 + j4];
            o[j4 + 0] += av * vv.x;
            o[j4 + 1] += av * vv.y;
            o[j4 + 2] += av * vv.z;
            o[j4 + 3] += av * vv.w;
        }
    }
    // fp16 store (8 x half2 = 16 values)
#pragma unroll
    for (int j4 = 0; j4 < 16; j4 += 4) {
        __half2 u = __floats2half2_rn(o[j4],     o[j4 + 1]);
        __half2 w = __floats2half2_rn(o[j4 + 2], o[j4 + 3]);
        uint2 pk;
        pk.x = *(const uint32_t*)&u;
        pk.y = *(const uint32_t*)&w;
        *(uint2*)(O + base + (size_t)r * tstride + c0 + j4) = pk;
    }
}

// ======================= launch =======================
extern "C" void kernel_launch(void* const* d_in, const int* in_sizes, int n_in,
                              void* d_out, int out_size)
{
    const float* X     = (const float*)d_in[0];
    const float* Wq    = (const float*)d_in[1];
    const float* bq    = (const float*)d_in[2];
    const float* gq    = (const float*)d_in[3];
    const float* betaq = (const float*)d_in[4];
    const float* mq    = (const float*)d_in[5];
    const float* vq    = (const float*)d_in[6];
    const float* Wk    = (const float*)d_in[7];
    const float* bk    = (const float*)d_in[8];
    const float* gk    = (const float*)d_in[9];
    const float* betak = (const float*)d_in[10];
    const float* mk    = (const float*)d_in[11];
    const float* vk    = (const float*)d_in[12];
    const float* Wv    = (const float*)d_in[13];
    const float* bv    = (const float*)d_in[14];
    const float* Wo    = (const float*)d_in[15];
    const float* bo    = (const float*)d_in[16];
    float* out = (float*)d_out;

    float *pQ, *pK, *pV, *pqsc, *pqsh, *pksc, *pksh;
    __half *pXh, *pAOh, *pwqh, *pwkh, *pwvh, *pwoh;
    cudaGetSymbolAddress((void**)&pQ,  g_Q);
    cudaGetSymbolAddress((void**)&pK,  g_K);
    cudaGetSymbolAddress((void**)&pV,  g_V);
    cudaGetSymbolAddress((void**)&pXh, g_Xh);
    cudaGetSymbolAddress((void**)&pAOh, g_AOh);
    cudaGetSymbolAddress((void**)&pwqh, g_wqh);
    cudaGetSymbolAddress((void**)&pwkh, g_wkh);
    cudaGetSymbolAddress((void**)&pwvh, g_wvh);
    cudaGetSymbolAddress((void**)&pwoh, g_woh);
    cudaGetSymbolAddress((void**)&pqsc, g_qsc);
    cudaGetSymbolAddress((void**)&pqsh, g_qsh);
    cudaGetSymbolAddress((void**)&pksc, g_ksc);
    cudaGetSymbolAddress((void**)&pksh, g_ksh);

    cudaFuncSetAttribute(mma_gemm, cudaFuncAttributeMaxDynamicSharedMemorySize, SMEM_G);
    cudaFuncSetAttribute(attn_kernel, cudaFuncAttributeMaxDynamicSharedMemorySize, SMEM_ATTN);

    // prep
    to_fp16<<<NELEM/4/256, 256>>>(X, pXh, NELEM);
    repack_conv_h<<<(KSz*Dd*Dd + 255)/256, 256>>>(Wq, pwqh);
    repack_conv_h<<<(KSz*Dd*Dd + 255)/256, 256>>>(Wk, pwkh);
    to_fp16_ws<<<(Dd*Dd)/4/256, 256>>>(Wv, pwvh, Dd*Dd);
    to_fp16_ws<<<(Dd*Dd)/4/256, 256>>>(Wo, pwoh, Dd*Dd);
    affine_k<<<2, 256>>>(bq, gq, betaq, mq, vq, pqsc, pqsh);
    affine_k<<<2, 256>>>(bk, gk, betak, mk, vk, pksc, pksh);

    // GEMMs via mma.sync (fp16 single-pass)
    dim3 grid(Dd/128, Bb*Tt);
    mma_gemm<<<grid, 256, SMEM_G>>>(pXh, pwqh, KSz, pqsc, pqsh, pQ);
    mma_gemm<<<grid, 256, SMEM_G>>>(pXh, pwkh, KSz, pksc, pksh, pK);
    mma_gemm<<<grid, 256, SMEM_G>>>(pXh, pwvh, 1, nullptr, bv, pV);

    // attention (fp32 compute, fp16 out)
    attn_kernel<<<Bb*Nn*KHh, 256, SMEM_ATTN>>>(pQ, pK, pV, pAOh);

    // output projection (reads fp16 AO directly)
    mma_gemm<<<grid, 256, SMEM_G>>>(pAOh, pwoh, 1, nullptr, bo, out);
}

// round 6
// speedup vs baseline: 7.4700x; 2.2223x over previous
#include <cuda_runtime.h>
#include <cuda_fp16.h>
#include <cstdint>
#include <math.h>

#define Bb 8
#define Tt 64
#define Nn 128
#define Dd 512
#define KHh 8
#define DHh 64
#define KSz 3
#define EPSv 1e-5f

#define NELEM (Bb*Tt*Nn*Dd)   // 16,777,216

// weight prescale (keeps fp16 weights away from subnormals)
#define WSCALE 1024.0f
#define WISCALE 0.0009765625f

// ======================= device scratch =======================
static __device__ __half g_Qh[NELEM];
static __device__ __half g_Kh[NELEM];
static __device__ __half g_Vh[NELEM];
static __device__ __half g_Xh[NELEM];
static __device__ __half g_AOh[NELEM];
static __device__ __half g_wqh[KSz*Dd*Dd];
static __device__ __half g_wkh[KSz*Dd*Dd];
static __device__ __half g_wvh[Dd*Dd];
static __device__ __half g_woh[Dd*Dd];
static __device__ float g_qsc[Dd], g_qsh[Dd];
static __device__ float g_ksc[Dd], g_ksh[Dd];

// ======================= helpers =======================
__device__ __forceinline__ uint32_t smem_u32(const void* p) {
    uint32_t a;
    asm("{ .reg .u64 t; cvta.to.shared.u64 t, %1; cvt.u32.u64 %0, t; }" : "=r"(a) : "l"(p));
    return a;
}
__device__ __forceinline__ uint32_t lds32(uint32_t a) {
    uint32_t v;
    asm volatile("ld.shared.b32 %0, [%1];" : "=r"(v) : "r"(a));
    return v;
}
__device__ __forceinline__ void cpasync16(uint32_t dst, const void* src) {
    asm volatile("cp.async.cg.shared.global [%0], [%1], 16;" :: "r"(dst), "l"(src));
}
#define CP_COMMIT() asm volatile("cp.async.commit_group;" ::: "memory")
#define CP_WAIT1()  asm volatile("cp.async.wait_group 1;" ::: "memory")

__device__ __forceinline__ void mma16816h(float* c, const uint32_t* a, uint32_t b0, uint32_t b1) {
    asm volatile(
        "mma.sync.aligned.m16n8k16.row.col.f32.f16.f16.f32 "
        "{%0,%1,%2,%3}, {%4,%5,%6,%7}, {%8,%9}, {%0,%1,%2,%3};"
        : "+f"(c[0]), "+f"(c[1]), "+f"(c[2]), "+f"(c[3])
        : "r"(a[0]), "r"(a[1]), "r"(a[2]), "r"(a[3]), "r"(b0), "r"(b1));
}
#define LDMX4(r, addr) \
    asm volatile("ldmatrix.sync.aligned.m8n8.x4.shared.b16 {%0,%1,%2,%3}, [%4];" \
        : "=r"((r)[0]), "=r"((r)[1]), "=r"((r)[2]), "=r"((r)[3]) : "r"(addr))
#define LDMX4T(r, addr) \
    asm volatile("ldmatrix.sync.aligned.m8n8.x4.trans.shared.b16 {%0,%1,%2,%3}, [%4];" \
        : "=r"((r)[0]), "=r"((r)[1]), "=r"((r)[2]), "=r"((r)[3]) : "r"(addr))

__device__ __forceinline__ uint32_t packh2(float a, float b) {
    __half2 h = __floats2half2_rn(a, b);
    return *(const uint32_t*)&h;
}

// ======================= prep kernels =======================
__global__ void to_fp16(const float* __restrict__ x, __half* __restrict__ y, int n)
{
    int i = (blockIdx.x * blockDim.x + threadIdx.x) * 4;
    if (i >= n) return;
    float4 v = *(const float4*)(x + i);
    uint2 o;
    o.x = packh2(v.x, v.y);
    o.y = packh2(v.z, v.w);
    *(uint2*)(y + i) = o;
}

__global__ void to_fp16_ws(const float* __restrict__ x, __half* __restrict__ y, int n)
{
    int i = (blockIdx.x * blockDim.x + threadIdx.x) * 4;
    if (i >= n) return;
    float4 v = *(const float4*)(x + i);
    uint2 o;
    o.x = packh2(v.x * WSCALE, v.y * WSCALE);
    o.y = packh2(v.z * WSCALE, v.w * WSCALE);
    *(uint2*)(y + i) = o;
}

// conv weight [e][d][s] -> fp16 [s][e][d], *WSCALE
__global__ void repack_conv_h(const float* __restrict__ W, __half* __restrict__ out)
{
    int idx = blockIdx.x * blockDim.x + threadIdx.x;
    if (idx >= KSz * Dd * Dd) return;
    int s = idx / (Dd * Dd);
    int r = idx - s * Dd * Dd;
    out[idx] = __float2half_rn(W[(size_t)r * KSz + s] * WSCALE);
}

__global__ void affine_k(const float* __restrict__ bc, const float* __restrict__ g,
                         const float* __restrict__ beta, const float* __restrict__ m,
                         const float* __restrict__ v, float* __restrict__ scale,
                         float* __restrict__ shift) {
    int e = blockIdx.x * blockDim.x + threadIdx.x;
    if (e >= Dd) return;
    float sc = g[e] * rsqrtf(v[e] + EPSv);
    scale[e] = sc;
    shift[e] = beta[e] + (bc[e] - m[e]) * sc;
}

// ======================= GEMM common =======================
#define TILE_B  (128 * 80)            // 10240 B per fp16 tile (K=32 chunk)

// ---------- fused Q+K conv GEMM ----------
#define QK_STAGE_B (3 * TILE_B)       // A, Bq, Bk
#define SMEM_QK (3 * QK_STAGE_B)      // 92160

struct StageSrcQK { const __half *a, *bq, *bk; };

__device__ __forceinline__ void issue_stage_qk(uint32_t sbuf, const StageSrcQK& s, int tid) {
#pragma unroll
    for (int j = 0; j < 2; ++j) {
        const int idx = tid + 256 * j;
        const int r   = idx >> 2;
        const int c16 = idx & 3;
        const uint32_t doff = (uint32_t)(r * 80 + c16 * 16);
        const size_t  goff = (size_t)r * Dd + c16 * 8;
        cpasync16(sbuf +              doff, s.a  + goff);
        cpasync16(sbuf +     TILE_B + doff, s.bq + goff);
        cpasync16(sbuf + 2 * TILE_B + doff, s.bk + goff);
    }
}

__global__ void __launch_bounds__(256)
mma_gemm_qk(const __half* __restrict__ A,
            const __half* __restrict__ Bq, const __half* __restrict__ Bk,
            const float* __restrict__ qsc, const float* __restrict__ qsh,
            const float* __restrict__ ksc, const float* __restrict__ ksh,
            __half* __restrict__ OutQ, __half* __restrict__ OutK)
{
    extern __shared__ __align__(16) char sm[];
    const uint32_t base_u = smem_u32(sm);

    const int tid = threadIdx.x;
    const int wid = tid >> 5;
    const int lane = tid & 31;
    const int qr = lane >> 2;
    const int qc = lane & 3;

    const int warp_m = (wid & 3) * 32;
    const int warp_n = (wid >> 2) * 64;

    const int e0 = blockIdx.x * 128;
    const int bt = blockIdx.y;
    const int t  = bt & (Tt - 1);

    int taps[KSz]; int ntv = 0;
    for (int s = 0; s < KSz; ++s)
        if (t - (KSz - 1) + s >= 0) taps[ntv++] = s;
    const int ns = ntv * 16;

    auto src_of = [&](int c) -> StageSrcQK {
        const int s  = taps[c >> 4];
        const int k0 = (c & 15) * 32;
        const size_t arow = (size_t)(bt - (KSz - 1) + s) * 128;
        const size_t boff = (size_t)s * Dd * Dd + (size_t)e0 * Dd + k0;
        StageSrcQK r;
        r.a  = A + arow * Dd + k0;
        r.bq = Bq + boff;
        r.bk = Bk + boff;
        return r;
    };

    float accq[2][8][4], acck[2][8][4];
#pragma unroll
    for (int i = 0; i < 2; ++i)
#pragma unroll
        for (int j = 0; j < 8; ++j)
#pragma unroll
            for (int q = 0; q < 4; ++q) { accq[i][j][q] = 0.0f; acck[i][j][q] = 0.0f; }

    issue_stage_qk(base_u, src_of(0), tid); CP_COMMIT();
    if (ns > 1) issue_stage_qk(base_u + QK_STAGE_B, src_of(1), tid);
    CP_COMMIT();

    const uint32_t a_base0 = (uint32_t)((warp_m + qr) * 80 + qc * 4);
    const uint32_t b_base0 = (uint32_t)((warp_n + qr) * 80 + qc * 4);

    int buf = 0;
    for (int c = 0; c < ns; ++c) {
        CP_WAIT1();
        __syncthreads();

        int buf2 = buf + 2; if (buf2 >= 3) buf2 -= 3;
        if (c + 2 < ns) issue_stage_qk(base_u + (uint32_t)buf2 * QK_STAGE_B, src_of(c + 2), tid);
        CP_COMMIT();

        const uint32_t sbuf = base_u + (uint32_t)buf * QK_STAGE_B;
        const uint32_t Ab = sbuf, Bqs = sbuf + TILE_B, Bks = sbuf + 2 * TILE_B;

#pragma unroll
        for (int kk = 0; kk < 2; ++kk) {
            const uint32_t kb = (uint32_t)(kk * 32);
            uint32_t ah[2][4];
#pragma unroll
            for (int mt = 0; mt < 2; ++mt) {
                const uint32_t ra = a_base0 + (uint32_t)(mt * 16 * 80) + kb;
                ah[mt][0] = lds32(Ab + ra);
                ah[mt][1] = lds32(Ab + ra + 8 * 80);
                ah[mt][2] = lds32(Ab + ra + 16);
                ah[mt][3] = lds32(Ab + ra + 8 * 80 + 16);
            }
#pragma unroll
            for (int nt = 0; nt < 8; ++nt) {
                const uint32_t rb = b_base0 + (uint32_t)(nt * 8 * 80) + kb;
                const uint32_t q0 = lds32(Bqs + rb);
                const uint32_t q1 = lds32(Bqs + rb + 16);
                const uint32_t k0r = lds32(Bks + rb);
                const uint32_t k1r = lds32(Bks + rb + 16);
#pragma unroll
                for (int mt = 0; mt < 2; ++mt) {
                    mma16816h(accq[mt][nt], ah[mt], q0, q1);
                    mma16816h(acck[mt][nt], ah[mt], k0r, k1r);
                }
            }
        }
        if (++buf >= 3) buf -= 3;
    }

    // epilogue: affine + fp16 stores for both Q and K
#pragma unroll
    for (int mt = 0; mt < 2; ++mt) {
#pragma unroll
        for (int nt = 0; nt < 8; ++nt) {
            const int col = warp_n + nt * 8 + 2 * qc;
            const int e   = e0 + col;
            const float qs0 = qsc[e] * WISCALE,     qs1 = qsc[e + 1] * WISCALE;
            const float qh0 = qsh[e],               qh1 = qsh[e + 1];
            const float ks0 = ksc[e] * WISCALE,     ks1 = ksc[e + 1] * WISCALE;
            const float kh0 = ksh[e],               kh1 = ksh[e + 1];
            const int row0 = warp_m + mt * 16 + qr;
            const size_t o0 = ((size_t)bt * 128 + row0) * Dd + e;
            const size_t o1 = ((size_t)bt * 128 + row0 + 8) * Dd + e;
            *(uint32_t*)(OutQ + o0) = packh2(accq[mt][nt][0] * qs0 + qh0, accq[mt][nt][1] * qs1 + qh1);
            *(uint32_t*)(OutQ + o1) = packh2(accq[mt][nt][2] * qs0 + qh0, accq[mt][nt][3] * qs1 + qh1);
            *(uint32_t*)(OutK + o0) = packh2(acck[mt][nt][0] * ks0 + kh0, acck[mt][nt][1] * ks1 + kh1);
            *(uint32_t*)(OutK + o1) = packh2(acck[mt][nt][2] * ks0 + kh0, acck[mt][nt][3] * ks1 + kh1);
        }
    }
}

// ---------- single-B GEMM (V projection / O projection) ----------
#define ONE_STAGE_B (2 * TILE_B)
#define SMEM_ONE (3 * ONE_STAGE_B)    // 61440

struct StageSrc1 { const __half *a, *b; };

__device__ __forceinline__ void issue_stage1(uint32_t sbuf, const StageSrc1& s, int tid) {
#pragma unroll
    for (int j = 0; j < 2; ++j) {
        const int idx = tid + 256 * j;
        const int r   = idx >> 2;
        const int c16 = idx & 3;
        const uint32_t doff = (uint32_t)(r * 80 + c16 * 16);
        const size_t  goff = (size_t)r * Dd + c16 * 8;
        cpasync16(sbuf +          doff, s.a + goff);
        cpasync16(sbuf + TILE_B + doff, s.b + goff);
    }
}

__global__ void __launch_bounds__(256, 2)
mma_gemm_one(const __half* __restrict__ A, const __half* __restrict__ B,
             const float* __restrict__ shift,
             float* __restrict__ OutF, __half* __restrict__ OutH)
{
    extern __shared__ __align__(16) char sm[];
    const uint32_t base_u = smem_u32(sm);

    const int tid = threadIdx.x;
    const int wid = tid >> 5;
    const int lane = tid & 31;
    const int qr = lane >> 2;
    const int qc = lane & 3;

    const int warp_m = (wid & 3) * 32;
    const int warp_n = (wid >> 2) * 64;

    const int e0 = blockIdx.x * 128;
    const int bt = blockIdx.y;
    const int ns = 16;

    auto src_of = [&](int c) -> StageSrc1 {
        const int k0 = c * 32;
        StageSrc1 r;
        r.a = A + (size_t)bt * 128 * Dd + k0;
        r.b = B + (size_t)e0 * Dd + k0;
        return r;
    };

    float acc[2][8][4];
#pragma unroll
    for (int i = 0; i < 2; ++i)
#pragma unroll
        for (int j = 0; j < 8; ++j)
#pragma unroll
            for (int q = 0; q < 4; ++q) acc[i][j][q] = 0.0f;

    issue_stage1(base_u, src_of(0), tid); CP_COMMIT();
    issue_stage1(base_u + ONE_STAGE_B, src_of(1), tid);
    CP_COMMIT();

    const uint32_t a_base0 = (uint32_t)((warp_m + qr) * 80 + qc * 4);
    const uint32_t b_base0 = (uint32_t)((warp_n + qr) * 80 + qc * 4);

    int buf = 0;
    for (int c = 0; c < ns; ++c) {
        CP_WAIT1();
        __syncthreads();

        int buf2 = buf + 2; if (buf2 >= 3) buf2 -= 3;
        if (c + 2 < ns) issue_stage1(base_u + (uint32_t)buf2 * ONE_STAGE_B, src_of(c + 2), tid);
        CP_COMMIT();

        const uint32_t sbuf = base_u + (uint32_t)buf * ONE_STAGE_B;
        const uint32_t Ab = sbuf, Bbs = sbuf + TILE_B;

#pragma unroll
        for (int kk = 0; kk < 2; ++kk) {
            const uint32_t kb = (uint32_t)(kk * 32);
            uint32_t ah[2][4];
#pragma unroll
            for (int mt = 0; mt < 2; ++mt) {
                const uint32_t ra = a_base0 + (uint32_t)(mt * 16 * 80) + kb;
                ah[mt][0] = lds32(Ab + ra);
                ah[mt][1] = lds32(Ab + ra + 8 * 80);
                ah[mt][2] = lds32(Ab + ra + 16);
                ah[mt][3] = lds32(Ab + ra + 8 * 80 + 16);
            }
#pragma unroll
            for (int nt = 0; nt < 8; ++nt) {
                const uint32_t rb = b_base0 + (uint32_t)(nt * 8 * 80) + kb;
                const uint32_t b0 = lds32(Bbs + rb);
                const uint32_t b1 = lds32(Bbs + rb + 16);
#pragma unroll
                for (int mt = 0; mt < 2; ++mt)
                    mma16816h(acc[mt][nt], ah[mt], b0, b1);
            }
        }
        if (++buf >= 3) buf -= 3;
    }

#pragma unroll
    for (int mt = 0; mt < 2; ++mt) {
#pragma unroll
        for (int nt = 0; nt < 8; ++nt) {
            const int col = warp_n + nt * 8 + 2 * qc;
            const int e   = e0 + col;
            const float h0 = shift[e], h1 = shift[e + 1];
            const int row0 = warp_m + mt * 16 + qr;
            const size_t o0 = ((size_t)bt * 128 + row0) * Dd + e;
            const size_t o1 = ((size_t)bt * 128 + row0 + 8) * Dd + e;
            const float v00 = acc[mt][nt][0] * WISCALE + h0;
            const float v01 = acc[mt][nt][1] * WISCALE + h1;
            const float v10 = acc[mt][nt][2] * WISCALE + h0;
            const float v11 = acc[mt][nt][3] * WISCALE + h1;
            if (OutF) {
                *(float2*)(OutF + o0) = make_float2(v00, v01);
                *(float2*)(OutF + o1) = make_float2(v10, v11);
            } else {
                *(uint32_t*)(OutH + o0) = packh2(v00, v01);
                *(uint32_t*)(OutH + o1) = packh2(v10, v11);
            }
        }
    }
}

// ======================= fp16 tensor-core attention =======================
// one block per (b, n, h); 4 warps; warp w computes rows m0=w*16 of the 64x64 head.
// smem: Q,K,V tiles 64 rows x 144B stride (128B data + 16B pad, ldmatrix-conflict-free)
#define ATT_ROW 144
#define ATT_MAT (64 * ATT_ROW)        // 9216

__global__ void __launch_bounds__(128) attn_h16(
    const __half* __restrict__ Q, const __half* __restrict__ K,
    const __half* __restrict__ V, __half* __restrict__ O)
{
    __shared__ __align__(16) char sm[3 * ATT_MAT];
    const uint32_t s_u = smem_u32(sm);
    const uint32_t Qs = s_u, Ks = s_u + ATT_MAT, Vs = s_u + 2 * ATT_MAT;

    const int blk = blockIdx.x;
    const int h = blk & (KHh - 1);
    const int n = (blk >> 3) & (Nn - 1);
    const int b = blk >> 10;

    const int tid = threadIdx.x;
    const int wid = tid >> 5;
    const int lane = tid & 31;

    const size_t tstride = (size_t)Nn * Dd;
    const size_t base = ((size_t)b * Tt * Nn + n) * Dd + h * DHh;

    // cooperative load: 512 16B-chunks per matrix, 4 per thread
#pragma unroll
    for (int i = 0; i < 4; ++i) {
        const int id = tid + 128 * i;
        const int r = id >> 3, c = id & 7;
        const size_t g = base + (size_t)r * tstride + c * 8;
        const uint32_t d = (uint32_t)(r * ATT_ROW + c * 16);
        *(uint4*)(sm + d)               = *(const uint4*)(Q + g);
        *(uint4*)(sm + ATT_MAT + d)     = *(const uint4*)(K + g);
        *(uint4*)(sm + 2 * ATT_MAT + d) = *(const uint4*)(V + g);
    }
    __syncthreads();

    const int m0 = wid * 16;

    // ---- S = Q @ K^T ----
    float s[8][4];
#pragma unroll
    for (int j = 0; j < 8; ++j)
#pragma unroll
        for (int q = 0; q < 4; ++q) s[j][q] = 0.0f;

#pragma unroll
    for (int ks = 0; ks < 4; ++ks) {
        const int k0 = ks * 16;
        uint32_t a[4];
        // A frag: lanes 0-15 -> rows m0+(lane&15) col k0; 16-31 -> +8 cols (16B)
        LDMX4(a, Qs + (uint32_t)((m0 + (lane & 15)) * ATT_ROW + 2 * k0 + (lane >> 4) * 16));
#pragma unroll
        for (int jp = 0; jp < 4; ++jp) {
            const int p0 = jp * 16;
            uint32_t kb[4];
            const int row = p0 + (lane & 7) + ((lane & 16) ? 8 : 0);
            const int colb = 2 * k0 + ((lane & 8) ? 16 : 0);
            LDMX4(kb, Ks + (uint32_t)(row * ATT_ROW + colb));
            mma16816h(s[2 * jp],     a, kb[0], kb[1]);
            mma16816h(s[2 * jp + 1], a, kb[2], kb[3]);
        }
    }

    // ---- softmax over 64 cols (rows g=m0+lane/4 and g+8) ----
    float mx0 = -1e30f, mx1 = -1e30f;
#pragma unroll
    for (int j = 0; j < 8; ++j) {
#pragma unroll
        for (int q = 0; q < 4; ++q) s[j][q] *= 0.125f;
        mx0 = fmaxf(mx0, fmaxf(s[j][0], s[j][1]));
        mx1 = fmaxf(mx1, fmaxf(s[j][2], s[j][3]));
    }
    mx0 = fmaxf(mx0, __shfl_xor_sync(0xffffffffu, mx0, 1));
    mx0 = fmaxf(mx0, __shfl_xor_sync(0xffffffffu, mx0, 2));
    mx1 = fmaxf(mx1, __shfl_xor_sync(0xffffffffu, mx1, 1));
    mx1 = fmaxf(mx1, __shfl_xor_sync(0xffffffffu, mx1, 2));

    float sum0 = 0.0f, sum1 = 0.0f;
#pragma unroll
    for (int j = 0; j < 8; ++j) {
        s[j][0] = __expf(s[j][0] - mx0);
        s[j][1] = __expf(s[j][1] - mx0);
        s[j][2] = __expf(s[j][2] - mx1);
        s[j][3] = __expf(s[j][3] - mx1);
        sum0 += s[j][0] + s[j][1];
        sum1 += s[j][2] + s[j][3];
    }
    sum0 += __shfl_xor_sync(0xffffffffu, sum0, 1);
    sum0 += __shfl_xor_sync(0xffffffffu, sum0, 2);
    sum1 += __shfl_xor_sync(0xffffffffu, sum1, 1);
    sum1 += __shfl_xor_sync(0xffffffffu, sum1, 2);
    const float inv0 = 1.0f / sum0;
    const float inv1 = 1.0f / sum1;

    // ---- O = P @ V ----
    float o[8][4];
#pragma unroll
    for (int j = 0; j < 8; ++j)
#pragma unroll
        for (int q = 0; q < 4; ++q) o[j][q] = 0.0f;

#pragma unroll
    for (int kk = 0; kk < 4; ++kk) {
        // A frag from normalized P (C-layout == A-layout, no shuffles)
        uint32_t a[4];
        a[0] = packh2(s[2 * kk][0] * inv0,     s[2 * kk][1] * inv0);
        a[1] = packh2(s[2 * kk][2] * inv1,     s[2 * kk][3] * inv1);
        a[2] = packh2(s[2 * kk + 1][0] * inv0, s[2 * kk + 1][1] * inv0);
        a[3] = packh2(s[2 * kk + 1][2] * inv1, s[2 * kk + 1][3] * inv1);
#pragma unroll
        for (int dp = 0; dp < 4; ++dp) {
            uint32_t vb[4];
            const int row = kk * 16 + (lane & 7) + ((lane & 8) ? 8 : 0);
            const int colb = dp * 32 + ((lane & 16) ? 16 : 0);
            LDMX4T(vb, Vs + (uint32_t)(row * ATT_ROW + colb));
            mma16816h(o[2 * dp],     a, vb[0], vb[1]);
            mma16816h(o[2 * dp + 1], a, vb[2], vb[3]);
        }
    }

    // ---- store O (fp16) ----
    const int g0 = m0 + (lane >> 2);
#pragma unroll
    for (int dt = 0; dt < 8; ++dt) {
        const int col = dt * 8 + 2 * (lane & 3);
        *(uint32_t*)(O + base + (size_t)g0 * tstride + col)       = packh2(o[dt][0], o[dt][1]);
        *(uint32_t*)(O + base + (size_t)(g0 + 8) * tstride + col) = packh2(o[dt][2], o[dt][3]);
    }
}

// ======================= launch =======================
extern "C" void kernel_launch(void* const* d_in, const int* in_sizes, int n_in,
                              void* d_out, int out_size)
{
    const float* X     = (const float*)d_in[0];
    const float* Wq    = (const float*)d_in[1];
    const float* bq    = (const float*)d_in[2];
    const float* gq    = (const float*)d_in[3];
    const float* betaq = (const float*)d_in[4];
    const float* mq    = (const float*)d_in[5];
    const float* vq    = (const float*)d_in[6];
    const float* Wk    = (const float*)d_in[7];
    const float* bk    = (const float*)d_in[8];
    const float* gk    = (const float*)d_in[9];
    const float* betak = (const float*)d_in[10];
    const float* mk    = (const float*)d_in[11];
    const float* vk    = (const float*)d_in[12];
    const float* Wv    = (const float*)d_in[13];
    const float* bv    = (const float*)d_in[14];
    const float* Wo    = (const float*)d_in[15];
    const float* bo    = (const float*)d_in[16];
    float* out = (float*)d_out;

    float *pqsc, *pqsh, *pksc, *pksh;
    __half *pQh, *pKh, *pVh, *pXh, *pAOh, *pwqh, *pwkh, *pwvh, *pwoh;
    cudaGetSymbolAddress((void**)&pQh, g_Qh);
    cudaGetSymbolAddress((void**)&pKh, g_Kh);
    cudaGetSymbolAddress((void**)&pVh, g_Vh);
    cudaGetSymbolAddress((void**)&pXh, g_Xh);
    cudaGetSymbolAddress((void**)&pAOh, g_AOh);
    cudaGetSymbolAddress((void**)&pwqh, g_wqh);
    cudaGetSymbolAddress((void**)&pwkh, g_wkh);
    cudaGetSymbolAddress((void**)&pwvh, g_wvh);
    cudaGetSymbolAddress((void**)&pwoh, g_woh);
    cudaGetSymbolAddress((void**)&pqsc, g_qsc);
    cudaGetSymbolAddress((void**)&pqsh, g_qsh);
    cudaGetSymbolAddress((void**)&pksc, g_ksc);
    cudaGetSymbolAddress((void**)&pksh, g_ksh);

    cudaFuncSetAttribute(mma_gemm_qk,  cudaFuncAttributeMaxDynamicSharedMemorySize, SMEM_QK);
    cudaFuncSetAttribute(mma_gemm_one, cudaFuncAttributeMaxDynamicSharedMemorySize, SMEM_ONE);

    // prep
    to_fp16<<<NELEM/4/256, 256>>>(X, pXh, NELEM);
    repack_conv_h<<<(KSz*Dd*Dd + 255)/256, 256>>>(Wq, pwqh);
    repack_conv_h<<<(KSz*Dd*Dd + 255)/256, 256>>>(Wk, pwkh);
    to_fp16_ws<<<(Dd*Dd)/4/256, 256>>>(Wv, pwvh, Dd*Dd);
    to_fp16_ws<<<(Dd*Dd)/4/256, 256>>>(Wo, pwoh, Dd*Dd);
    affine_k<<<2, 256>>>(bq, gq, betaq, mq, vq, pqsc, pqsh);
    affine_k<<<2, 256>>>(bk, gk, betak, mk, vk, pksc, pksh);

    dim3 grid(Dd/128, Bb*Tt);
    // fused Q+K conv GEMM -> fp16
    mma_gemm_qk<<<grid, 256, SMEM_QK>>>(pXh, pwqh, pwkh, pqsc, pqsh, pksc, pksh, pQh, pKh);
    // V projection -> fp16
    mma_gemm_one<<<grid, 256, SMEM_ONE>>>(pXh, pwvh, bv, nullptr, pVh);

    // tensor-core attention -> fp16 AO
    attn_h16<<<Bb*Nn*KHh, 128>>>(pQh, pKh, pVh, pAOh);

    // output projection -> fp32
    mma_gemm_one<<<grid, 256, SMEM_ONE>>>(pAOh, pwoh, bo, out, nullptr);
}